// round 7
// baseline (speedup 1.0000x reference)
#include <cuda_runtime.h>
#include <cuda_bf16.h>
#include <cstdint>

// ---------------- problem constants ----------------
#define S       2048
#define DIM     4096
#define NH      32
#define HD      128
#define QKV_N   6144
#define K_OFF   4096
#define V_OFF   5120

// ---------------- scratch (device globals) ----------------
__device__ __nv_bfloat16 g_qh[S * QKV_N], g_ql[S * QKV_N];
__device__ __nv_bfloat16 g_xh[S * DIM],  g_xl[S * DIM];
__device__ __nv_bfloat16 g_wh[QKV_N * DIM], g_wl[QKV_N * DIM];
__device__ __nv_bfloat16 g_oh[DIM * DIM], g_ol[DIM * DIM];
__device__ __nv_bfloat16 g_ah[S * DIM],  g_al[S * DIM];

// ---------------- helpers ----------------
__device__ __forceinline__ uint32_t smem_u32(const void* p) {
    uint32_t a;
    asm("{ .reg .u64 t; cvta.to.shared.u64 t, %1; cvt.u32.u64 %0, t; }" : "=r"(a) : "l"(p));
    return a;
}
__device__ __forceinline__ void cp16(uint32_t dst, const void* src) {
    asm volatile("cp.async.cg.shared.global [%0], [%1], 16;" :: "r"(dst), "l"(src));
}
__device__ __forceinline__ void cp_commit() {
    asm volatile("cp.async.commit_group;");
}
template <int N>
__device__ __forceinline__ void cp_wait() {
    asm volatile("cp.async.wait_group %0;" :: "n"(N));
}
__device__ __forceinline__ void ldm_x4(uint32_t* r, uint32_t addr) {
    asm volatile("ldmatrix.sync.aligned.m8n8.x4.shared.b16 {%0,%1,%2,%3}, [%4];"
                 : "=r"(r[0]), "=r"(r[1]), "=r"(r[2]), "=r"(r[3]) : "r"(addr));
}
__device__ __forceinline__ void ldm_x4t(uint32_t* r, uint32_t addr) {
    asm volatile("ldmatrix.sync.aligned.m8n8.x4.trans.shared.b16 {%0,%1,%2,%3}, [%4];"
                 : "=r"(r[0]), "=r"(r[1]), "=r"(r[2]), "=r"(r[3]) : "r"(addr));
}
__device__ __forceinline__ void mma16816(float* c, const uint32_t* a, uint32_t b0, uint32_t b1) {
    asm volatile(
        "mma.sync.aligned.m16n8k16.row.col.f32.bf16.bf16.f32 "
        "{%0,%1,%2,%3}, {%4,%5,%6,%7}, {%8,%9}, {%0,%1,%2,%3};"
        : "+f"(c[0]), "+f"(c[1]), "+f"(c[2]), "+f"(c[3])
        : "r"(a[0]), "r"(a[1]), "r"(a[2]), "r"(a[3]), "r"(b0), "r"(b1));
}
__device__ __forceinline__ void pack_hl(float x, float y, uint32_t& h, uint32_t& l) {
    __nv_bfloat162 hb = __floats2bfloat162_rn(x, y);
    float hx = __bfloat162float(hb.x), hy = __bfloat162float(hb.y);
    __nv_bfloat162 lb = __floats2bfloat162_rn(x - hx, y - hy);
    h = *reinterpret_cast<uint32_t*>(&hb);
    l = *reinterpret_cast<uint32_t*>(&lb);
}

// ---------------- split fp32 -> (bf16 hi, bf16 lo) ----------------
__global__ void split_kernel(const float* __restrict__ src,
                             __nv_bfloat16* __restrict__ hi,
                             __nv_bfloat16* __restrict__ lo, int n4)
{
    int i = blockIdx.x * blockDim.x + threadIdx.x;
    if (i >= n4) return;
    float4 v = ((const float4*)src)[i];
    __nv_bfloat16 h0 = __float2bfloat16(v.x), h1 = __float2bfloat16(v.y);
    __nv_bfloat16 h2 = __float2bfloat16(v.z), h3 = __float2bfloat16(v.w);
    __nv_bfloat16 l0 = __float2bfloat16(v.x - __bfloat162float(h0));
    __nv_bfloat16 l1 = __float2bfloat16(v.y - __bfloat162float(h1));
    __nv_bfloat16 l2 = __float2bfloat16(v.z - __bfloat162float(h2));
    __nv_bfloat16 l3 = __float2bfloat16(v.w - __bfloat162float(h3));
    __nv_bfloat162 hv0 = {h0, h1}, hv1 = {h2, h3};
    __nv_bfloat162 lv0 = {l0, l1}, lv1 = {l2, l3};
    ((__nv_bfloat162*)hi)[2 * i]     = hv0;
    ((__nv_bfloat162*)hi)[2 * i + 1] = hv1;
    ((__nv_bfloat162*)lo)[2 * i]     = lv0;
    ((__nv_bfloat162*)lo)[2 * i + 1] = lv1;
}

// ---------------- bf16x3 GEMM, CTA 128x256, warp 64x64, term-major MMA order ----------------
#define A_HI 0
#define A_LO (16 * 1024)
#define B_HI (32 * 1024)
#define B_LO (64 * 1024)
#define STG_B (96 * 1024)
#define GEMM_SMEM (2 * STG_B)

__global__ __launch_bounds__(256, 1) void gemm_bf16x3(
    const __nv_bfloat16* __restrict__ Ah, const __nv_bfloat16* __restrict__ Al,
    const __nv_bfloat16* __restrict__ Bh, const __nv_bfloat16* __restrict__ Bl,
    float* __restrict__ C, int K, int ldc, int mode,
    const float* __restrict__ cs, const float* __restrict__ sn,
    __nv_bfloat16* __restrict__ Oh, __nv_bfloat16* __restrict__ Ol)
{
    extern __shared__ __align__(1024) char smc[];
    const uint32_t sbase = smem_u32(smc);

    const int tid  = threadIdx.x;
    const int lane = tid & 31;
    const int wid  = tid >> 5;
    const int wm   = wid & 1;
    const int wn   = wid >> 1;
    const int m0 = blockIdx.x * 128;
    const int n0 = blockIdx.y * 256;

    const int grp = lane >> 3;
    const int rin = lane & 7;

    float acc[4][8][4];
    #pragma unroll
    for (int i = 0; i < 4; i++)
        #pragma unroll
        for (int j = 0; j < 8; j++)
            #pragma unroll
            for (int q = 0; q < 4; q++) acc[i][j][q] = 0.f;

    const int nk = K >> 6;

    auto load_chunk = [&](int buf, int it) {
        const int k0 = it << 6;
        const uint32_t sb = sbase + buf * STG_B;
        #pragma unroll
        for (int i = 0; i < 4; i++) {
            int id = tid + i * 256;
            int row = id >> 3, c16 = id & 7;
            uint32_t so = (uint32_t)(row * 128) + ((uint32_t)(c16 ^ (row & 7)) << 4);
            size_t g = (size_t)(m0 + row) * K + k0 + c16 * 8;
            cp16(sb + A_HI + so, Ah + g);
            cp16(sb + A_LO + so, Al + g);
        }
        #pragma unroll
        for (int i = 0; i < 8; i++) {
            int id = tid + i * 256;
            int row = id >> 3, c16 = id & 7;
            uint32_t so = (uint32_t)(row * 128) + ((uint32_t)(c16 ^ (row & 7)) << 4);
            size_t g = (size_t)(n0 + row) * K + k0 + c16 * 8;
            cp16(sb + B_HI + so, Bh + g);
            cp16(sb + B_LO + so, Bl + g);
        }
        cp_commit();
    };

    load_chunk(0, 0);

    for (int it = 0; it < nk; it++) {
        const int buf = it & 1;
        if (it + 1 < nk) { load_chunk(buf ^ 1, it + 1); cp_wait<1>(); }
        else             { cp_wait<0>(); }
        __syncthreads();

        const uint32_t sA = sbase + buf * STG_B;
        const uint32_t sB = sA + B_HI;
        #pragma unroll
        for (int kc = 0; kc < 4; kc++) {
            const int c16 = kc * 2 + (grp >> 1);

            uint32_t ah[4][4], al[4][4];
            #pragma unroll
            for (int am = 0; am < 4; am++) {
                int row = wm * 64 + am * 16 + rin + (grp & 1) * 8;
                uint32_t so = (uint32_t)(row * 128) + ((uint32_t)(c16 ^ (row & 7)) << 4);
                ldm_x4(ah[am], sA + so);
                ldm_x4(al[am], sA + A_LO + so);
            }

            #pragma unroll
            for (int bt = 0; bt < 4; bt++) {
                int row = wn * 64 + bt * 16 + rin + (grp & 1) * 8;
                uint32_t so = (uint32_t)(row * 128) + ((uint32_t)(c16 ^ (row & 7)) << 4);
                uint32_t bh[4], bl[4];
                ldm_x4(bh, sB + so);
                ldm_x4(bl, sB + (B_LO - B_HI) + so);
                // term-major: 8 independent MMAs per term -> acc reuse distance 8
                #pragma unroll
                for (int am = 0; am < 4; am++) {
                    mma16816(acc[am][2 * bt],     ah[am], bh[0], bh[2]);
                    mma16816(acc[am][2 * bt + 1], ah[am], bh[1], bh[3]);
                }
                #pragma unroll
                for (int am = 0; am < 4; am++) {
                    mma16816(acc[am][2 * bt],     al[am], bh[0], bh[2]);
                    mma16816(acc[am][2 * bt + 1], al[am], bh[1], bh[3]);
                }
                #pragma unroll
                for (int am = 0; am < 4; am++) {
                    mma16816(acc[am][2 * bt],     ah[am], bl[0], bl[2]);
                    mma16816(acc[am][2 * bt + 1], ah[am], bl[1], bl[3]);
                }
            }
        }
        __syncthreads();
    }

    if (mode == 0) {
        #pragma unroll
        for (int am = 0; am < 4; am++) {
            int row = m0 + wm * 64 + am * 16 + (lane >> 2);
            #pragma unroll
            for (int bn = 0; bn < 8; bn++) {
                int col = n0 + wn * 64 + bn * 8 + (lane & 3) * 2;
                *(float2*)&C[(size_t)row * ldc + col]       = make_float2(acc[am][bn][0], acc[am][bn][1]);
                *(float2*)&C[(size_t)(row + 8) * ldc + col] = make_float2(acc[am][bn][2], acc[am][bn][3]);
            }
        }
    } else {
        #pragma unroll
        for (int am = 0; am < 4; am++) {
            int row = m0 + wm * 64 + am * 16 + (lane >> 2);
            #pragma unroll
            for (int bn = 0; bn < 8; bn++) {
                int col = n0 + wn * 64 + bn * 8 + (lane & 3) * 2;
                int i = (col & (HD - 1)) >> 1;
                bool rope = col < V_OFF;
                #pragma unroll
                for (int half = 0; half < 2; half++) {
                    int r = row + half * 8;
                    float v0 = acc[am][bn][2 * half], v1 = acc[am][bn][2 * half + 1];
                    if (rope) {
                        float c = cs[r * 64 + i], si = sn[r * 64 + i];
                        float t0 = v0 * c - v1 * si;
                        float t1 = v0 * si + v1 * c;
                        v0 = t0; v1 = t1;
                    }
                    uint32_t hb, lb;
                    pack_hl(v0, v1, hb, lb);
                    *(uint32_t*)&Oh[(size_t)r * ldc + col] = hb;
                    *(uint32_t*)&Ol[(size_t)r * ldc + col] = lb;
                }
            }
        }
    }
}

// ---------------- tensor-core flash attention (bf16x3, causal, GQA 4:1) ----------------
#define ATT_SMEM (192 * 1024)

__global__ __launch_bounds__(256, 1) void attn_mma(
    const __nv_bfloat16* __restrict__ qh_g, const __nv_bfloat16* __restrict__ ql_g,
    __nv_bfloat16* __restrict__ ah_g, __nv_bfloat16* __restrict__ al_g)
{
    extern __shared__ __align__(1024) char smb[];
    const uint32_t sb = smem_u32(smb);
    const uint32_t sQh = sb, sQl = sb + 32 * 1024;

    const int tid = threadIdx.x, lane = tid & 31, wid = tid >> 5;
    const int qt = (int)gridDim.x - 1 - (int)blockIdx.x;
    const int h = blockIdx.y, kvh = h >> 2;
    const int q0 = qt * 128;
    const int wq = wid * 16;

    #pragma unroll
    for (int i = 0; i < 8; i++) {
        int ch = tid + i * 256;
        int row = ch >> 4, c16 = ch & 15;
        uint32_t so = (uint32_t)(row * 256) + (uint32_t)((c16 ^ (row & 7)) << 4);
        size_t g = (size_t)(q0 + row) * QKV_N + h * HD + c16 * 8;
        cp16(sQh + so, qh_g + g);
        cp16(sQl + so, ql_g + g);
    }
    cp_commit();

    const int ktmax = 2 * qt + 1;
    auto load_kv = [&](int kt) {
        const uint32_t st = sb + 64 * 1024 + (uint32_t)(kt & 1) * 64 * 1024;
        const int k0 = kt * 64;
        #pragma unroll
        for (int i = 0; i < 4; i++) {
            int ch = tid + i * 256;
            int row = ch >> 4, c16 = ch & 15;
            uint32_t so = (uint32_t)(row * 256) + (uint32_t)((c16 ^ (row & 7)) << 4);
            size_t kb = (size_t)(k0 + row) * QKV_N + kvh * HD + c16 * 8;
            cp16(st + so,             qh_g + kb + K_OFF);
            cp16(st + 16 * 1024 + so, ql_g + kb + K_OFF);
            cp16(st + 32 * 1024 + so, qh_g + kb + V_OFF);
            cp16(st + 48 * 1024 + so, ql_g + kb + V_OFF);
        }
        cp_commit();
    };
    load_kv(0);

    float oacc[16][4];
    #pragma unroll
    for (int a = 0; a < 16; a++)
        #pragma unroll
        for (int q = 0; q < 4; q++) oacc[a][q] = 0.f;
    float m0 = -1e30f, m1 = -1e30f, l0 = 0.f, l1 = 0.f;
    const float kscale = 0.08838834764831845f * 1.44269504088896f;

    const int rin = lane & 7, grp = lane >> 3;
    const int arow = wq + rin + (grp & 1) * 8;
    const int r0 = lane >> 2;

    for (int kt = 0; kt <= ktmax; kt++) {
        if (kt < ktmax) { load_kv(kt + 1); cp_wait<1>(); }
        else            { cp_wait<0>(); }
        __syncthreads();

        const bool skip = (kt * 64) > (q0 + wq + 15);
        if (!skip) {
            const uint32_t st = sb + 64 * 1024 + (uint32_t)(kt & 1) * 64 * 1024;

            float sc[8][4];
            #pragma unroll
            for (int a = 0; a < 8; a++)
                #pragma unroll
                for (int q = 0; q < 4; q++) sc[a][q] = 0.f;

            // QK^T: bt-pairs, term-major (acc reuse distance 4)
            #pragma unroll
            for (int k16 = 0; k16 < 8; k16++) {
                const int c16 = k16 * 2 + (grp >> 1);
                uint32_t aoff = (uint32_t)(arow * 256) + (uint32_t)((c16 ^ (arow & 7)) << 4);
                uint32_t aqh[4], aql[4];
                ldm_x4(aqh, sQh + aoff);
                ldm_x4(aql, sQl + aoff);
                #pragma unroll
                for (int bp = 0; bp < 2; bp++) {
                    uint32_t bh[2][4], bl[2][4];
                    #pragma unroll
                    for (int t = 0; t < 2; t++) {
                        int brow = (bp * 2 + t) * 16 + rin + (grp & 1) * 8;
                        uint32_t boff = (uint32_t)(brow * 256) + (uint32_t)((c16 ^ (brow & 7)) << 4);
                        ldm_x4(bh[t], st + boff);
                        ldm_x4(bl[t], st + 16 * 1024 + boff);
                    }
                    #pragma unroll
                    for (int t = 0; t < 2; t++) {
                        int b = bp * 2 + t;
                        mma16816(sc[2 * b],     aqh, bh[t][0], bh[t][2]);
                        mma16816(sc[2 * b + 1], aqh, bh[t][1], bh[t][3]);
                    }
                    #pragma unroll
                    for (int t = 0; t < 2; t++) {
                        int b = bp * 2 + t;
                        mma16816(sc[2 * b],     aql, bh[t][0], bh[t][2]);
                        mma16816(sc[2 * b + 1], aql, bh[t][1], bh[t][3]);
                    }
                    #pragma unroll
                    for (int t = 0; t < 2; t++) {
                        int b = bp * 2 + t;
                        mma16816(sc[2 * b],     aqh, bl[t][0], bl[t][2]);
                        mma16816(sc[2 * b + 1], aqh, bl[t][1], bl[t][3]);
                    }
                }
            }

            if (kt * 64 + 63 > q0 + wq) {
                int qr0 = q0 + wq + r0, qr1 = qr0 + 8;
                int cb = kt * 64 + 2 * (lane & 3);
                #pragma unroll
                for (int a = 0; a < 8; a++) {
                    int c0 = cb + a * 8, c1 = c0 + 1;
                    if (c0 > qr0) sc[a][0] = -1e30f;
                    if (c1 > qr0) sc[a][1] = -1e30f;
                    if (c0 > qr1) sc[a][2] = -1e30f;
                    if (c1 > qr1) sc[a][3] = -1e30f;
                }
            }

            float mx0 = -1e30f, mx1 = -1e30f;
            #pragma unroll
            for (int a = 0; a < 8; a++) {
                mx0 = fmaxf(mx0, fmaxf(sc[a][0], sc[a][1]));
                mx1 = fmaxf(mx1, fmaxf(sc[a][2], sc[a][3]));
            }
            mx0 = fmaxf(mx0, __shfl_xor_sync(0xffffffffu, mx0, 1));
            mx0 = fmaxf(mx0, __shfl_xor_sync(0xffffffffu, mx0, 2));
            mx1 = fmaxf(mx1, __shfl_xor_sync(0xffffffffu, mx1, 1));
            mx1 = fmaxf(mx1, __shfl_xor_sync(0xffffffffu, mx1, 2));
            float nm0 = fmaxf(m0, mx0), nm1 = fmaxf(m1, mx1);
            float corr0 = exp2f((m0 - nm0) * kscale);
            float corr1 = exp2f((m1 - nm1) * kscale);
            float s0 = 0.f, s1 = 0.f;
            #pragma unroll
            for (int a = 0; a < 8; a++) {
                sc[a][0] = exp2f((sc[a][0] - nm0) * kscale);
                sc[a][1] = exp2f((sc[a][1] - nm0) * kscale);
                sc[a][2] = exp2f((sc[a][2] - nm1) * kscale);
                sc[a][3] = exp2f((sc[a][3] - nm1) * kscale);
                s0 += sc[a][0] + sc[a][1];
                s1 += sc[a][2] + sc[a][3];
            }
            s0 += __shfl_xor_sync(0xffffffffu, s0, 1);
            s0 += __shfl_xor_sync(0xffffffffu, s0, 2);
            s1 += __shfl_xor_sync(0xffffffffu, s1, 1);
            s1 += __shfl_xor_sync(0xffffffffu, s1, 2);
            l0 = l0 * corr0 + s0;
            l1 = l1 * corr1 + s1;
            m0 = nm0; m1 = nm1;
            #pragma unroll
            for (int a = 0; a < 16; a++) {
                oacc[a][0] *= corr0; oacc[a][1] *= corr0;
                oacc[a][2] *= corr1; oacc[a][3] *= corr1;
            }

            // PV: d-pairs, term-major (oacc reuse distance 4)
            #pragma unroll
            for (int t = 0; t < 4; t++) {
                uint32_t ph[4], pl[4];
                pack_hl(sc[2 * t][0],     sc[2 * t][1],     ph[0], pl[0]);
                pack_hl(sc[2 * t][2],     sc[2 * t][3],     ph[1], pl[1]);
                pack_hl(sc[2 * t + 1][0], sc[2 * t + 1][1], ph[2], pl[2]);
                pack_hl(sc[2 * t + 1][2], sc[2 * t + 1][3], ph[3], pl[3]);
                #pragma unroll
                for (int dp = 0; dp < 4; dp++) {
                    uint32_t vh[2][4], vl[2][4];
                    #pragma unroll
                    for (int u = 0; u < 2; u++) {
                        int d = dp * 2 + u;
                        int vrow = t * 16 + (grp & 1) * 8 + rin;
                        int c16 = d * 2 + (grp >> 1);
                        uint32_t voff = (uint32_t)(vrow * 256) + (uint32_t)((c16 ^ (vrow & 7)) << 4);
                        ldm_x4t(vh[u], st + 32 * 1024 + voff);
                        ldm_x4t(vl[u], st + 48 * 1024 + voff);
                    }
                    #pragma unroll
                    for (int u = 0; u < 2; u++) {
                        int d = dp * 2 + u;
                        mma16816(oacc[2 * d],     ph, vh[u][0], vh[u][1]);
                        mma16816(oacc[2 * d + 1], ph, vh[u][2], vh[u][3]);
                    }
                    #pragma unroll
                    for (int u = 0; u < 2; u++) {
                        int d = dp * 2 + u;
                        mma16816(oacc[2 * d],     pl, vh[u][0], vh[u][1]);
                        mma16816(oacc[2 * d + 1], pl, vh[u][2], vh[u][3]);
                    }
                    #pragma unroll
                    for (int u = 0; u < 2; u++) {
                        int d = dp * 2 + u;
                        mma16816(oacc[2 * d],     ph, vl[u][0], vl[u][1]);
                        mma16816(oacc[2 * d + 1], ph, vl[u][2], vl[u][3]);
                    }
                }
            }
        }
        __syncthreads();
    }

    float inv0 = 1.f / l0, inv1 = 1.f / l1;
    int gr0 = q0 + wq + r0, gr1 = gr0 + 8;
    #pragma unroll
    for (int a = 0; a < 16; a++) {
        int d0 = a * 8 + 2 * (lane & 3);
        float v0 = oacc[a][0] * inv0, v1 = oacc[a][1] * inv0;
        float w0 = oacc[a][2] * inv1, w1 = oacc[a][3] * inv1;
        uint32_t hb, lb;
        pack_hl(v0, v1, hb, lb);
        *(uint32_t*)&ah_g[(size_t)gr0 * DIM + h * HD + d0] = hb;
        *(uint32_t*)&al_g[(size_t)gr0 * DIM + h * HD + d0] = lb;
        pack_hl(w0, w1, hb, lb);
        *(uint32_t*)&ah_g[(size_t)gr1 * DIM + h * HD + d0] = hb;
        *(uint32_t*)&al_g[(size_t)gr1 * DIM + h * HD + d0] = lb;
    }
}

// ---------------- launch ----------------
extern "C" void kernel_launch(void* const* d_in, const int* in_sizes, int n_in,
                              void* d_out, int out_size)
{
    const float* x  = (const float*)d_in[0];
    const float* fc = (const float*)d_in[1];
    const float* fs = (const float*)d_in[2];
    const float* wq = (const float*)d_in[5];
    const float* wk = (const float*)d_in[6];
    const float* wv = (const float*)d_in[7];
    const float* wo = (const float*)d_in[8];
    float* out = (float*)d_out;

    __nv_bfloat16 *qh, *ql, *xh, *xl, *wh, *wl, *oh, *ol, *ah, *al;
    cudaGetSymbolAddress((void**)&qh, g_qh);  cudaGetSymbolAddress((void**)&ql, g_ql);
    cudaGetSymbolAddress((void**)&xh, g_xh);  cudaGetSymbolAddress((void**)&xl, g_xl);
    cudaGetSymbolAddress((void**)&wh, g_wh);  cudaGetSymbolAddress((void**)&wl, g_wl);
    cudaGetSymbolAddress((void**)&oh, g_oh);  cudaGetSymbolAddress((void**)&ol, g_ol);
    cudaGetSymbolAddress((void**)&ah, g_ah);  cudaGetSymbolAddress((void**)&al, g_al);

    cudaFuncSetAttribute(gemm_bf16x3, cudaFuncAttributeMaxDynamicSharedMemorySize, GEMM_SMEM);
    cudaFuncSetAttribute(attn_mma, cudaFuncAttributeMaxDynamicSharedMemorySize, ATT_SMEM);

    dim3 blk(256);
    int n4x = S * DIM / 4;
    split_kernel<<<(n4x + 255) / 256, blk>>>(x, xh, xl, n4x);
    int n4q = DIM * DIM / 4;
    split_kernel<<<(n4q + 255) / 256, blk>>>(wq, wh, wl, n4q);
    int n4k = 1024 * DIM / 4;
    split_kernel<<<(n4k + 255) / 256, blk>>>(wk, wh + (size_t)4096 * DIM, wl + (size_t)4096 * DIM, n4k);
    split_kernel<<<(n4k + 255) / 256, blk>>>(wv, wh + (size_t)5120 * DIM, wl + (size_t)5120 * DIM, n4k);
    split_kernel<<<(n4q + 255) / 256, blk>>>(wo, oh, ol, n4q);

    gemm_bf16x3<<<dim3(S / 128, QKV_N / 256), blk, GEMM_SMEM>>>(
        xh, xl, wh, wl, nullptr, DIM, QKV_N, 1, fc, fs, qh, ql);

    attn_mma<<<dim3(S / 128, NH), blk, ATT_SMEM>>>(qh, ql, ah, al);

    gemm_bf16x3<<<dim3(S / 128, DIM / 256), blk, GEMM_SMEM>>>(
        ah, al, oh, ol, out, DIM, DIM, 0, nullptr, nullptr, nullptr, nullptr);
}

// round 8
// speedup vs baseline: 1.3253x; 1.3253x over previous
#include <cuda_runtime.h>
#include <cuda_bf16.h>
#include <cuda_fp16.h>
#include <cstdint>

// ---------------- problem constants ----------------
#define S       2048
#define DIM     4096
#define NH      32
#define HD      128
#define QKV_N   6144
#define K_OFF   4096
#define V_OFF   5120

// ---------------- scratch (device globals) ----------------
__device__ __nv_bfloat16 g_qh[S * QKV_N], g_ql[S * QKV_N];   // rope'd qkv, bf16 hi/lo (attention input)
__device__ __half g_xh[S * DIM],  g_xl[S * DIM];             // x fp16 hi/lo
__device__ __half g_wh[QKV_N * DIM];                         // packed wq|wk|wv fp16 hi
__device__ __half g_oh[DIM * DIM];                           // wo fp16 hi
__device__ __half g_ah[S * DIM],  g_al[S * DIM];             // attention out fp16 hi/lo

// ---------------- helpers ----------------
__device__ __forceinline__ uint32_t smem_u32(const void* p) {
    uint32_t a;
    asm("{ .reg .u64 t; cvta.to.shared.u64 t, %1; cvt.u32.u64 %0, t; }" : "=r"(a) : "l"(p));
    return a;
}
__device__ __forceinline__ void cp16(uint32_t dst, const void* src) {
    asm volatile("cp.async.cg.shared.global [%0], [%1], 16;" :: "r"(dst), "l"(src));
}
__device__ __forceinline__ void cp_commit() {
    asm volatile("cp.async.commit_group;");
}
template <int N>
__device__ __forceinline__ void cp_wait() {
    asm volatile("cp.async.wait_group %0;" :: "n"(N));
}
__device__ __forceinline__ void ldm_x4(uint32_t* r, uint32_t addr) {
    asm volatile("ldmatrix.sync.aligned.m8n8.x4.shared.b16 {%0,%1,%2,%3}, [%4];"
                 : "=r"(r[0]), "=r"(r[1]), "=r"(r[2]), "=r"(r[3]) : "r"(addr));
}
__device__ __forceinline__ void ldm_x4t(uint32_t* r, uint32_t addr) {
    asm volatile("ldmatrix.sync.aligned.m8n8.x4.trans.shared.b16 {%0,%1,%2,%3}, [%4];"
                 : "=r"(r[0]), "=r"(r[1]), "=r"(r[2]), "=r"(r[3]) : "r"(addr));
}
__device__ __forceinline__ void mma_bf16(float* c, const uint32_t* a, uint32_t b0, uint32_t b1) {
    asm volatile(
        "mma.sync.aligned.m16n8k16.row.col.f32.bf16.bf16.f32 "
        "{%0,%1,%2,%3}, {%4,%5,%6,%7}, {%8,%9}, {%0,%1,%2,%3};"
        : "+f"(c[0]), "+f"(c[1]), "+f"(c[2]), "+f"(c[3])
        : "r"(a[0]), "r"(a[1]), "r"(a[2]), "r"(a[3]), "r"(b0), "r"(b1));
}
__device__ __forceinline__ void mma_f16(float* c, const uint32_t* a, uint32_t b0, uint32_t b1) {
    asm volatile(
        "mma.sync.aligned.m16n8k16.row.col.f32.f16.f16.f32 "
        "{%0,%1,%2,%3}, {%4,%5,%6,%7}, {%8,%9}, {%0,%1,%2,%3};"
        : "+f"(c[0]), "+f"(c[1]), "+f"(c[2]), "+f"(c[3])
        : "r"(a[0]), "r"(a[1]), "r"(a[2]), "r"(a[3]), "r"(b0), "r"(b1));
}
__device__ __forceinline__ void pack_hl_bf16(float x, float y, uint32_t& h, uint32_t& l) {
    __nv_bfloat162 hb = __floats2bfloat162_rn(x, y);
    float hx = __bfloat162float(hb.x), hy = __bfloat162float(hb.y);
    __nv_bfloat162 lb = __floats2bfloat162_rn(x - hx, y - hy);
    h = *reinterpret_cast<uint32_t*>(&hb);
    l = *reinterpret_cast<uint32_t*>(&lb);
}
__device__ __forceinline__ void pack_hl_f16(float x, float y, uint32_t& h, uint32_t& l) {
    __half2 hb = __floats2half2_rn(x, y);
    float hx = __low2float(hb), hy = __high2float(hb);
    __half2 lb = __floats2half2_rn(x - hx, y - hy);
    h = *reinterpret_cast<uint32_t*>(&hb);
    l = *reinterpret_cast<uint32_t*>(&lb);
}

// ---------------- splits ----------------
__global__ void split_f16hl(const float* __restrict__ src,
                            __half* __restrict__ hi, __half* __restrict__ lo, int n4)
{
    int i = blockIdx.x * blockDim.x + threadIdx.x;
    if (i >= n4) return;
    float4 v = ((const float4*)src)[i];
    __half2 h0 = __floats2half2_rn(v.x, v.y);
    __half2 h1 = __floats2half2_rn(v.z, v.w);
    __half2 l0 = __floats2half2_rn(v.x - __low2float(h0), v.y - __high2float(h0));
    __half2 l1 = __floats2half2_rn(v.z - __low2float(h1), v.w - __high2float(h1));
    ((__half2*)hi)[2 * i]     = h0;
    ((__half2*)hi)[2 * i + 1] = h1;
    ((__half2*)lo)[2 * i]     = l0;
    ((__half2*)lo)[2 * i + 1] = l1;
}
__global__ void split_f16h(const float* __restrict__ src, __half* __restrict__ hi, int n4)
{
    int i = blockIdx.x * blockDim.x + threadIdx.x;
    if (i >= n4) return;
    float4 v = ((const float4*)src)[i];
    ((__half2*)hi)[2 * i]     = __floats2half2_rn(v.x, v.y);
    ((__half2*)hi)[2 * i + 1] = __floats2half2_rn(v.z, v.w);
}

// ---------------- fp16x2 GEMM, CTA 128x256, warp 64x64, 3-stage pipeline ----------------
// C[m,n] = sum_k A[m,k]*B[n,k] via Ah*Bh + Al*Bh  (B hi-only fp16)
#define A_HI 0
#define A_LO (16 * 1024)
#define B_HI (32 * 1024)
#define STG_B (64 * 1024)
#define GEMM_SMEM (3 * STG_B)

__global__ __launch_bounds__(256, 1) void gemm_f16x2(
    const __half* __restrict__ Ah, const __half* __restrict__ Al,
    const __half* __restrict__ Bh,
    float* __restrict__ C, int K, int ldc, int mode,
    const float* __restrict__ cs, const float* __restrict__ sn,
    __nv_bfloat16* __restrict__ Oh, __nv_bfloat16* __restrict__ Ol)
{
    extern __shared__ __align__(1024) char smc[];
    const uint32_t sbase = smem_u32(smc);

    const int tid  = threadIdx.x;
    const int lane = tid & 31;
    const int wid  = tid >> 5;
    const int wm   = wid & 1;
    const int wn   = wid >> 1;
    const int m0 = blockIdx.x * 128;
    const int n0 = blockIdx.y * 256;

    const int grp = lane >> 3;
    const int rin = lane & 7;

    float acc[4][8][4];
    #pragma unroll
    for (int i = 0; i < 4; i++)
        #pragma unroll
        for (int j = 0; j < 8; j++)
            #pragma unroll
            for (int q = 0; q < 4; q++) acc[i][j][q] = 0.f;

    const int nk = K >> 6;

    auto load_chunk = [&](int it) {
        const int k0 = it << 6;
        const uint32_t sb = sbase + (uint32_t)(it % 3) * STG_B;
        #pragma unroll
        for (int i = 0; i < 4; i++) {                 // A hi/lo: 1024 lines each
            int id = tid + i * 256;
            int row = id >> 3, c16 = id & 7;
            uint32_t so = (uint32_t)(row * 128) + ((uint32_t)(c16 ^ (row & 7)) << 4);
            size_t g = (size_t)(m0 + row) * K + k0 + c16 * 8;
            cp16(sb + A_HI + so, Ah + g);
            cp16(sb + A_LO + so, Al + g);
        }
        #pragma unroll
        for (int i = 0; i < 8; i++) {                 // B hi: 2048 lines
            int id = tid + i * 256;
            int row = id >> 3, c16 = id & 7;
            uint32_t so = (uint32_t)(row * 128) + ((uint32_t)(c16 ^ (row & 7)) << 4);
            size_t g = (size_t)(n0 + row) * K + k0 + c16 * 8;
            cp16(sb + B_HI + so, Bh + g);
        }
        cp_commit();
    };

    load_chunk(0);
    if (nk > 1) load_chunk(1); else cp_commit();

    for (int it = 0; it < nk; it++) {
        if (it + 2 < nk) load_chunk(it + 2); else cp_commit();
        cp_wait<2>();
        __syncthreads();

        const uint32_t sA = sbase + (uint32_t)(it % 3) * STG_B;
        const uint32_t sB = sA + B_HI;
        #pragma unroll
        for (int kc = 0; kc < 4; kc++) {
            const int c16 = kc * 2 + (grp >> 1);

            uint32_t ah[4][4], al[4][4];
            #pragma unroll
            for (int am = 0; am < 4; am++) {
                int row = wm * 64 + am * 16 + rin + (grp & 1) * 8;
                uint32_t so = (uint32_t)(row * 128) + ((uint32_t)(c16 ^ (row & 7)) << 4);
                ldm_x4(ah[am], sA + so);
                ldm_x4(al[am], sA + A_LO + so);
            }

            #pragma unroll
            for (int bt = 0; bt < 4; bt++) {
                int row = wn * 64 + bt * 16 + rin + (grp & 1) * 8;
                uint32_t so = (uint32_t)(row * 128) + ((uint32_t)(c16 ^ (row & 7)) << 4);
                uint32_t bh[4];
                ldm_x4(bh, sB + so);
                #pragma unroll
                for (int am = 0; am < 4; am++) {
                    mma_f16(acc[am][2 * bt],     ah[am], bh[0], bh[2]);
                    mma_f16(acc[am][2 * bt + 1], ah[am], bh[1], bh[3]);
                }
                #pragma unroll
                for (int am = 0; am < 4; am++) {
                    mma_f16(acc[am][2 * bt],     al[am], bh[0], bh[2]);
                    mma_f16(acc[am][2 * bt + 1], al[am], bh[1], bh[3]);
                }
            }
        }
        __syncthreads();
    }

    if (mode == 0) {
        #pragma unroll
        for (int am = 0; am < 4; am++) {
            int row = m0 + wm * 64 + am * 16 + (lane >> 2);
            #pragma unroll
            for (int bn = 0; bn < 8; bn++) {
                int col = n0 + wn * 64 + bn * 8 + (lane & 3) * 2;
                *(float2*)&C[(size_t)row * ldc + col]       = make_float2(acc[am][bn][0], acc[am][bn][1]);
                *(float2*)&C[(size_t)(row + 8) * ldc + col] = make_float2(acc[am][bn][2], acc[am][bn][3]);
            }
        }
    } else {
        // RoPE (cols < V_OFF) + bf16 hi/lo split -> Oh/Ol
        #pragma unroll
        for (int am = 0; am < 4; am++) {
            int row = m0 + wm * 64 + am * 16 + (lane >> 2);
            #pragma unroll
            for (int bn = 0; bn < 8; bn++) {
                int col = n0 + wn * 64 + bn * 8 + (lane & 3) * 2;
                int i = (col & (HD - 1)) >> 1;
                bool rope = col < V_OFF;
                #pragma unroll
                for (int half = 0; half < 2; half++) {
                    int r = row + half * 8;
                    float v0 = acc[am][bn][2 * half], v1 = acc[am][bn][2 * half + 1];
                    if (rope) {
                        float c = cs[r * 64 + i], si = sn[r * 64 + i];
                        float t0 = v0 * c - v1 * si;
                        float t1 = v0 * si + v1 * c;
                        v0 = t0; v1 = t1;
                    }
                    uint32_t hb, lb;
                    pack_hl_bf16(v0, v1, hb, lb);
                    *(uint32_t*)&Oh[(size_t)r * ldc + col] = hb;
                    *(uint32_t*)&Ol[(size_t)r * ldc + col] = lb;
                }
            }
        }
    }
}

// ---------------- tensor-core flash attention (bf16x3, causal, GQA 4:1) ----------------
#define ATT_SMEM (192 * 1024)

__global__ __launch_bounds__(256, 1) void attn_mma(
    const __nv_bfloat16* __restrict__ qh_g, const __nv_bfloat16* __restrict__ ql_g,
    __half* __restrict__ ah_g, __half* __restrict__ al_g)
{
    extern __shared__ __align__(1024) char smb[];
    const uint32_t sb = smem_u32(smb);
    const uint32_t sQh = sb, sQl = sb + 32 * 1024;

    const int tid = threadIdx.x, lane = tid & 31, wid = tid >> 5;
    const int qt = (int)gridDim.x - 1 - (int)blockIdx.x;
    const int h = blockIdx.y, kvh = h >> 2;
    const int q0 = qt * 128;
    const int wq = wid * 16;

    #pragma unroll
    for (int i = 0; i < 8; i++) {
        int ch = tid + i * 256;
        int row = ch >> 4, c16 = ch & 15;
        uint32_t so = (uint32_t)(row * 256) + (uint32_t)((c16 ^ (row & 7)) << 4);
        size_t g = (size_t)(q0 + row) * QKV_N + h * HD + c16 * 8;
        cp16(sQh + so, qh_g + g);
        cp16(sQl + so, ql_g + g);
    }
    cp_commit();

    const int ktmax = 2 * qt + 1;
    auto load_kv = [&](int kt) {
        const uint32_t st = sb + 64 * 1024 + (uint32_t)(kt & 1) * 64 * 1024;
        const int k0 = kt * 64;
        #pragma unroll
        for (int i = 0; i < 4; i++) {
            int ch = tid + i * 256;
            int row = ch >> 4, c16 = ch & 15;
            uint32_t so = (uint32_t)(row * 256) + (uint32_t)((c16 ^ (row & 7)) << 4);
            size_t kb = (size_t)(k0 + row) * QKV_N + kvh * HD + c16 * 8;
            cp16(st + so,             qh_g + kb + K_OFF);
            cp16(st + 16 * 1024 + so, ql_g + kb + K_OFF);
            cp16(st + 32 * 1024 + so, qh_g + kb + V_OFF);
            cp16(st + 48 * 1024 + so, ql_g + kb + V_OFF);
        }
        cp_commit();
    };
    load_kv(0);

    float oacc[16][4];
    #pragma unroll
    for (int a = 0; a < 16; a++)
        #pragma unroll
        for (int q = 0; q < 4; q++) oacc[a][q] = 0.f;
    float m0 = -1e30f, m1 = -1e30f, l0 = 0.f, l1 = 0.f;
    const float kscale = 0.08838834764831845f * 1.44269504088896f;

    const int rin = lane & 7, grp = lane >> 3;
    const int arow = wq + rin + (grp & 1) * 8;
    const int r0 = lane >> 2;

    for (int kt = 0; kt <= ktmax; kt++) {
        if (kt < ktmax) { load_kv(kt + 1); cp_wait<1>(); }
        else            { cp_wait<0>(); }
        __syncthreads();

        const bool skip = (kt * 64) > (q0 + wq + 15);
        if (!skip) {
            const uint32_t st = sb + 64 * 1024 + (uint32_t)(kt & 1) * 64 * 1024;

            float sc[8][4];
            #pragma unroll
            for (int a = 0; a < 8; a++)
                #pragma unroll
                for (int q = 0; q < 4; q++) sc[a][q] = 0.f;

            #pragma unroll
            for (int k16 = 0; k16 < 8; k16++) {
                const int c16 = k16 * 2 + (grp >> 1);
                uint32_t aoff = (uint32_t)(arow * 256) + (uint32_t)((c16 ^ (arow & 7)) << 4);
                uint32_t aqh[4], aql[4];
                ldm_x4(aqh, sQh + aoff);
                ldm_x4(aql, sQl + aoff);
                #pragma unroll
                for (int bp = 0; bp < 2; bp++) {
                    uint32_t bh[2][4], bl[2][4];
                    #pragma unroll
                    for (int t = 0; t < 2; t++) {
                        int brow = (bp * 2 + t) * 16 + rin + (grp & 1) * 8;
                        uint32_t boff = (uint32_t)(brow * 256) + (uint32_t)((c16 ^ (brow & 7)) << 4);
                        ldm_x4(bh[t], st + boff);
                        ldm_x4(bl[t], st + 16 * 1024 + boff);
                    }
                    #pragma unroll
                    for (int t = 0; t < 2; t++) {
                        int b = bp * 2 + t;
                        mma_bf16(sc[2 * b],     aqh, bh[t][0], bh[t][2]);
                        mma_bf16(sc[2 * b + 1], aqh, bh[t][1], bh[t][3]);
                    }
                    #pragma unroll
                    for (int t = 0; t < 2; t++) {
                        int b = bp * 2 + t;
                        mma_bf16(sc[2 * b],     aql, bh[t][0], bh[t][2]);
                        mma_bf16(sc[2 * b + 1], aql, bh[t][1], bh[t][3]);
                    }
                    #pragma unroll
                    for (int t = 0; t < 2; t++) {
                        int b = bp * 2 + t;
                        mma_bf16(sc[2 * b],     aqh, bl[t][0], bl[t][2]);
                        mma_bf16(sc[2 * b + 1], aqh, bl[t][1], bl[t][3]);
                    }
                }
            }

            if (kt * 64 + 63 > q0 + wq) {
                int qr0 = q0 + wq + r0, qr1 = qr0 + 8;
                int cb = kt * 64 + 2 * (lane & 3);
                #pragma unroll
                for (int a = 0; a < 8; a++) {
                    int c0 = cb + a * 8, c1 = c0 + 1;
                    if (c0 > qr0) sc[a][0] = -1e30f;
                    if (c1 > qr0) sc[a][1] = -1e30f;
                    if (c0 > qr1) sc[a][2] = -1e30f;
                    if (c1 > qr1) sc[a][3] = -1e30f;
                }
            }

            float mx0 = -1e30f, mx1 = -1e30f;
            #pragma unroll
            for (int a = 0; a < 8; a++) {
                mx0 = fmaxf(mx0, fmaxf(sc[a][0], sc[a][1]));
                mx1 = fmaxf(mx1, fmaxf(sc[a][2], sc[a][3]));
            }
            mx0 = fmaxf(mx0, __shfl_xor_sync(0xffffffffu, mx0, 1));
            mx0 = fmaxf(mx0, __shfl_xor_sync(0xffffffffu, mx0, 2));
            mx1 = fmaxf(mx1, __shfl_xor_sync(0xffffffffu, mx1, 1));
            mx1 = fmaxf(mx1, __shfl_xor_sync(0xffffffffu, mx1, 2));
            float nm0 = fmaxf(m0, mx0), nm1 = fmaxf(m1, mx1);
            float corr0 = exp2f((m0 - nm0) * kscale);
            float corr1 = exp2f((m1 - nm1) * kscale);
            float s0 = 0.f, s1 = 0.f;
            #pragma unroll
            for (int a = 0; a < 8; a++) {
                sc[a][0] = exp2f((sc[a][0] - nm0) * kscale);
                sc[a][1] = exp2f((sc[a][1] - nm0) * kscale);
                sc[a][2] = exp2f((sc[a][2] - nm1) * kscale);
                sc[a][3] = exp2f((sc[a][3] - nm1) * kscale);
                s0 += sc[a][0] + sc[a][1];
                s1 += sc[a][2] + sc[a][3];
            }
            s0 += __shfl_xor_sync(0xffffffffu, s0, 1);
            s0 += __shfl_xor_sync(0xffffffffu, s0, 2);
            s1 += __shfl_xor_sync(0xffffffffu, s1, 1);
            s1 += __shfl_xor_sync(0xffffffffu, s1, 2);
            l0 = l0 * corr0 + s0;
            l1 = l1 * corr1 + s1;
            m0 = nm0; m1 = nm1;
            #pragma unroll
            for (int a = 0; a < 16; a++) {
                oacc[a][0] *= corr0; oacc[a][1] *= corr0;
                oacc[a][2] *= corr1; oacc[a][3] *= corr1;
            }

            #pragma unroll
            for (int t = 0; t < 4; t++) {
                uint32_t ph[4], pl[4];
                pack_hl_bf16(sc[2 * t][0],     sc[2 * t][1],     ph[0], pl[0]);
                pack_hl_bf16(sc[2 * t][2],     sc[2 * t][3],     ph[1], pl[1]);
                pack_hl_bf16(sc[2 * t + 1][0], sc[2 * t + 1][1], ph[2], pl[2]);
                pack_hl_bf16(sc[2 * t + 1][2], sc[2 * t + 1][3], ph[3], pl[3]);
                #pragma unroll
                for (int dp = 0; dp < 4; dp++) {
                    uint32_t vh[2][4], vl[2][4];
                    #pragma unroll
                    for (int u = 0; u < 2; u++) {
                        int d = dp * 2 + u;
                        int vrow = t * 16 + (grp & 1) * 8 + rin;
                        int c16 = d * 2 + (grp >> 1);
                        uint32_t voff = (uint32_t)(vrow * 256) + (uint32_t)((c16 ^ (vrow & 7)) << 4);
                        ldm_x4t(vh[u], st + 32 * 1024 + voff);
                        ldm_x4t(vl[u], st + 48 * 1024 + voff);
                    }
                    #pragma unroll
                    for (int u = 0; u < 2; u++) {
                        int d = dp * 2 + u;
                        mma_bf16(oacc[2 * d],     ph, vh[u][0], vh[u][1]);
                        mma_bf16(oacc[2 * d + 1], ph, vh[u][2], vh[u][3]);
                    }
                    #pragma unroll
                    for (int u = 0; u < 2; u++) {
                        int d = dp * 2 + u;
                        mma_bf16(oacc[2 * d],     pl, vh[u][0], vh[u][1]);
                        mma_bf16(oacc[2 * d + 1], pl, vh[u][2], vh[u][3]);
                    }
                    #pragma unroll
                    for (int u = 0; u < 2; u++) {
                        int d = dp * 2 + u;
                        mma_bf16(oacc[2 * d],     ph, vl[u][0], vl[u][1]);
                        mma_bf16(oacc[2 * d + 1], ph, vl[u][2], vl[u][3]);
                    }
                }
            }
        }
        __syncthreads();
    }

    // epilogue: normalize, write fp16 hi/lo (feeds fp16x2 out-proj)
    float inv0 = 1.f / l0, inv1 = 1.f / l1;
    int gr0 = q0 + wq + r0, gr1 = gr0 + 8;
    #pragma unroll
    for (int a = 0; a < 16; a++) {
        int d0 = a * 8 + 2 * (lane & 3);
        float v0 = oacc[a][0] * inv0, v1 = oacc[a][1] * inv0;
        float w0 = oacc[a][2] * inv1, w1 = oacc[a][3] * inv1;
        uint32_t hb, lb;
        pack_hl_f16(v0, v1, hb, lb);
        *(uint32_t*)&ah_g[(size_t)gr0 * DIM + h * HD + d0] = hb;
        *(uint32_t*)&al_g[(size_t)gr0 * DIM + h * HD + d0] = lb;
        pack_hl_f16(w0, w1, hb, lb);
        *(uint32_t*)&ah_g[(size_t)gr1 * DIM + h * HD + d0] = hb;
        *(uint32_t*)&al_g[(size_t)gr1 * DIM + h * HD + d0] = lb;
    }
}

// ---------------- launch ----------------
extern "C" void kernel_launch(void* const* d_in, const int* in_sizes, int n_in,
                              void* d_out, int out_size)
{
    const float* x  = (const float*)d_in[0];
    const float* fc = (const float*)d_in[1];
    const float* fs = (const float*)d_in[2];
    const float* wq = (const float*)d_in[5];
    const float* wk = (const float*)d_in[6];
    const float* wv = (const float*)d_in[7];
    const float* wo = (const float*)d_in[8];
    float* out = (float*)d_out;

    __nv_bfloat16 *qh, *ql;
    __half *xh, *xl, *wh, *oh, *ah, *al;
    cudaGetSymbolAddress((void**)&qh, g_qh);  cudaGetSymbolAddress((void**)&ql, g_ql);
    cudaGetSymbolAddress((void**)&xh, g_xh);  cudaGetSymbolAddress((void**)&xl, g_xl);
    cudaGetSymbolAddress((void**)&wh, g_wh);  cudaGetSymbolAddress((void**)&oh, g_oh);
    cudaGetSymbolAddress((void**)&ah, g_ah);  cudaGetSymbolAddress((void**)&al, g_al);

    cudaFuncSetAttribute(gemm_f16x2, cudaFuncAttributeMaxDynamicSharedMemorySize, GEMM_SMEM);
    cudaFuncSetAttribute(attn_mma, cudaFuncAttributeMaxDynamicSharedMemorySize, ATT_SMEM);

    dim3 blk(256);
    int n4x = S * DIM / 4;
    split_f16hl<<<(n4x + 255) / 256, blk>>>(x, xh, xl, n4x);
    int n4q = DIM * DIM / 4;
    split_f16h<<<(n4q + 255) / 256, blk>>>(wq, wh, n4q);
    int n4k = 1024 * DIM / 4;
    split_f16h<<<(n4k + 255) / 256, blk>>>(wk, wh + (size_t)4096 * DIM, n4k);
    split_f16h<<<(n4k + 255) / 256, blk>>>(wv, wh + (size_t)5120 * DIM, n4k);
    split_f16h<<<(n4q + 255) / 256, blk>>>(wo, oh, n4q);

    // QKV projection (fp16x2) with fused RoPE + bf16 hi/lo split epilogue
    gemm_f16x2<<<dim3(S / 128, QKV_N / 256), blk, GEMM_SMEM>>>(
        xh, xl, wh, nullptr, DIM, QKV_N, 1, fc, fs, qh, ql);

    // tensor-core attention (bf16x3) -> fp16 hi/lo output
    attn_mma<<<dim3(S / 128, NH), blk, ATT_SMEM>>>(qh, ql, ah, al);

    // output projection (fp16x2) -> fp32 out
    gemm_f16x2<<<dim3(S / 128, DIM / 256), blk, GEMM_SMEM>>>(
        ah, al, oh, out, DIM, DIM, 0, nullptr, nullptr, nullptr, nullptr);
}

// round 9
// speedup vs baseline: 1.4901x; 1.1244x over previous
#include <cuda_runtime.h>
#include <cuda_bf16.h>
#include <cuda_fp16.h>
#include <cstdint>

// ---------------- problem constants ----------------
#define S       2048
#define DIM     4096
#define NH      32
#define HD      128
#define QKV_N   6144
#define K_OFF   4096
#define V_OFF   5120

// ---------------- scratch (device globals) ----------------
__device__ __half g_qh[S * QKV_N], g_ql[S * QKV_N];   // rope'd qkv, fp16 hi/lo
__device__ __half g_xh[S * DIM],  g_xl[S * DIM];      // x fp16 hi/lo
__device__ __half g_wh[QKV_N * DIM];                  // packed wq|wk|wv fp16 hi
__device__ __half g_oh[DIM * DIM];                    // wo fp16 hi
__device__ __half g_ah[S * DIM];                      // attention out fp16 hi (1-term out-proj)

// ---------------- helpers ----------------
__device__ __forceinline__ uint32_t smem_u32(const void* p) {
    uint32_t a;
    asm("{ .reg .u64 t; cvta.to.shared.u64 t, %1; cvt.u32.u64 %0, t; }" : "=r"(a) : "l"(p));
    return a;
}
__device__ __forceinline__ void cp16(uint32_t dst, const void* src) {
    asm volatile("cp.async.cg.shared.global [%0], [%1], 16;" :: "r"(dst), "l"(src));
}
__device__ __forceinline__ void cp_commit() {
    asm volatile("cp.async.commit_group;");
}
template <int N>
__device__ __forceinline__ void cp_wait() {
    asm volatile("cp.async.wait_group %0;" :: "n"(N));
}
__device__ __forceinline__ void ldm_x4(uint32_t* r, uint32_t addr) {
    asm volatile("ldmatrix.sync.aligned.m8n8.x4.shared.b16 {%0,%1,%2,%3}, [%4];"
                 : "=r"(r[0]), "=r"(r[1]), "=r"(r[2]), "=r"(r[3]) : "r"(addr));
}
__device__ __forceinline__ void ldm_x4t(uint32_t* r, uint32_t addr) {
    asm volatile("ldmatrix.sync.aligned.m8n8.x4.trans.shared.b16 {%0,%1,%2,%3}, [%4];"
                 : "=r"(r[0]), "=r"(r[1]), "=r"(r[2]), "=r"(r[3]) : "r"(addr));
}
__device__ __forceinline__ void mma_f16(float* c, const uint32_t* a, uint32_t b0, uint32_t b1) {
    asm volatile(
        "mma.sync.aligned.m16n8k16.row.col.f32.f16.f16.f32 "
        "{%0,%1,%2,%3}, {%4,%5,%6,%7}, {%8,%9}, {%0,%1,%2,%3};"
        : "+f"(c[0]), "+f"(c[1]), "+f"(c[2]), "+f"(c[3])
        : "r"(a[0]), "r"(a[1]), "r"(a[2]), "r"(a[3]), "r"(b0), "r"(b1));
}
__device__ __forceinline__ void pack_hl_f16(float x, float y, uint32_t& h, uint32_t& l) {
    __half2 hb = __floats2half2_rn(x, y);
    float hx = __low2float(hb), hy = __high2float(hb);
    __half2 lb = __floats2half2_rn(x - hx, y - hy);
    h = *reinterpret_cast<uint32_t*>(&hb);
    l = *reinterpret_cast<uint32_t*>(&lb);
}
__device__ __forceinline__ uint32_t pack_f16(float x, float y) {
    __half2 hb = __floats2half2_rn(x, y);
    return *reinterpret_cast<uint32_t*>(&hb);
}

// ---------------- splits ----------------
__global__ void split_f16hl(const float* __restrict__ src,
                            __half* __restrict__ hi, __half* __restrict__ lo, int n4)
{
    int i = blockIdx.x * blockDim.x + threadIdx.x;
    if (i >= n4) return;
    float4 v = ((const float4*)src)[i];
    __half2 h0 = __floats2half2_rn(v.x, v.y);
    __half2 h1 = __floats2half2_rn(v.z, v.w);
    __half2 l0 = __floats2half2_rn(v.x - __low2float(h0), v.y - __high2float(h0));
    __half2 l1 = __floats2half2_rn(v.z - __low2float(h1), v.w - __high2float(h1));
    ((__half2*)hi)[2 * i]     = h0;
    ((__half2*)hi)[2 * i + 1] = h1;
    ((__half2*)lo)[2 * i]     = l0;
    ((__half2*)lo)[2 * i + 1] = l1;
}
__global__ void split_f16h(const float* __restrict__ src, __half* __restrict__ hi, int n4)
{
    int i = blockIdx.x * blockDim.x + threadIdx.x;
    if (i >= n4) return;
    float4 v = ((const float4*)src)[i];
    ((__half2*)hi)[2 * i]     = __floats2half2_rn(v.x, v.y);
    ((__half2*)hi)[2 * i + 1] = __floats2half2_rn(v.z, v.w);
}

// ---------------- fp16 GEMM, CTA 128x256, warp 64x64, 3-stage pipeline ----------------
// terms==2: C = Ah*Bh + Al*Bh ; terms==1: C = Ah*Bh
// mode 0: write fp32 C; mode 1: RoPE (cols < V_OFF) + fp16 hi/lo split into Oh/Ol
#define A_HI 0
#define A_LO (16 * 1024)
#define B_HI (32 * 1024)
#define STG_B (64 * 1024)
#define GEMM_SMEM (3 * STG_B)

__global__ __launch_bounds__(256, 1) void gemm_f16(
    const __half* __restrict__ Ah, const __half* __restrict__ Al,
    const __half* __restrict__ Bh,
    float* __restrict__ C, int K, int ldc, int mode, int terms,
    const float* __restrict__ cs, const float* __restrict__ sn,
    __half* __restrict__ Oh, __half* __restrict__ Ol)
{
    extern __shared__ __align__(1024) char smc[];
    const uint32_t sbase = smem_u32(smc);

    const int tid  = threadIdx.x;
    const int lane = tid & 31;
    const int wid  = tid >> 5;
    const int wm   = wid & 1;
    const int wn   = wid >> 1;
    const int m0 = blockIdx.x * 128;
    const int n0 = blockIdx.y * 256;

    const int grp = lane >> 3;
    const int rin = lane & 7;

    float acc[4][8][4];
    #pragma unroll
    for (int i = 0; i < 4; i++)
        #pragma unroll
        for (int j = 0; j < 8; j++)
            #pragma unroll
            for (int q = 0; q < 4; q++) acc[i][j][q] = 0.f;

    const int nk = K >> 6;

    auto load_chunk = [&](int it) {
        const int k0 = it << 6;
        const uint32_t sb = sbase + (uint32_t)(it % 3) * STG_B;
        #pragma unroll
        for (int i = 0; i < 4; i++) {
            int id = tid + i * 256;
            int row = id >> 3, c16 = id & 7;
            uint32_t so = (uint32_t)(row * 128) + ((uint32_t)(c16 ^ (row & 7)) << 4);
            size_t g = (size_t)(m0 + row) * K + k0 + c16 * 8;
            cp16(sb + A_HI + so, Ah + g);
            if (terms == 2) cp16(sb + A_LO + so, Al + g);
        }
        #pragma unroll
        for (int i = 0; i < 8; i++) {
            int id = tid + i * 256;
            int row = id >> 3, c16 = id & 7;
            uint32_t so = (uint32_t)(row * 128) + ((uint32_t)(c16 ^ (row & 7)) << 4);
            size_t g = (size_t)(n0 + row) * K + k0 + c16 * 8;
            cp16(sb + B_HI + so, Bh + g);
        }
        cp_commit();
    };

    load_chunk(0);
    if (nk > 1) load_chunk(1); else cp_commit();

    for (int it = 0; it < nk; it++) {
        if (it + 2 < nk) load_chunk(it + 2); else cp_commit();
        cp_wait<2>();
        __syncthreads();

        const uint32_t sA = sbase + (uint32_t)(it % 3) * STG_B;
        const uint32_t sB = sA + B_HI;
        #pragma unroll
        for (int kc = 0; kc < 4; kc++) {
            const int c16 = kc * 2 + (grp >> 1);

            uint32_t ah[4][4], al[4][4];
            #pragma unroll
            for (int am = 0; am < 4; am++) {
                int row = wm * 64 + am * 16 + rin + (grp & 1) * 8;
                uint32_t so = (uint32_t)(row * 128) + ((uint32_t)(c16 ^ (row & 7)) << 4);
                ldm_x4(ah[am], sA + so);
                if (terms == 2) ldm_x4(al[am], sA + A_LO + so);
            }

            #pragma unroll
            for (int bt = 0; bt < 4; bt++) {
                int row = wn * 64 + bt * 16 + rin + (grp & 1) * 8;
                uint32_t so = (uint32_t)(row * 128) + ((uint32_t)(c16 ^ (row & 7)) << 4);
                uint32_t bh[4];
                ldm_x4(bh, sB + so);
                #pragma unroll
                for (int am = 0; am < 4; am++) {
                    mma_f16(acc[am][2 * bt],     ah[am], bh[0], bh[2]);
                    mma_f16(acc[am][2 * bt + 1], ah[am], bh[1], bh[3]);
                }
                if (terms == 2) {
                    #pragma unroll
                    for (int am = 0; am < 4; am++) {
                        mma_f16(acc[am][2 * bt],     al[am], bh[0], bh[2]);
                        mma_f16(acc[am][2 * bt + 1], al[am], bh[1], bh[3]);
                    }
                }
            }
        }
        __syncthreads();
    }

    if (mode == 0) {
        #pragma unroll
        for (int am = 0; am < 4; am++) {
            int row = m0 + wm * 64 + am * 16 + (lane >> 2);
            #pragma unroll
            for (int bn = 0; bn < 8; bn++) {
                int col = n0 + wn * 64 + bn * 8 + (lane & 3) * 2;
                *(float2*)&C[(size_t)row * ldc + col]       = make_float2(acc[am][bn][0], acc[am][bn][1]);
                *(float2*)&C[(size_t)(row + 8) * ldc + col] = make_float2(acc[am][bn][2], acc[am][bn][3]);
            }
        }
    } else {
        // RoPE (cols < V_OFF) + fp16 hi/lo split -> Oh/Ol
        #pragma unroll
        for (int am = 0; am < 4; am++) {
            int row = m0 + wm * 64 + am * 16 + (lane >> 2);
            #pragma unroll
            for (int bn = 0; bn < 8; bn++) {
                int col = n0 + wn * 64 + bn * 8 + (lane & 3) * 2;
                int i = (col & (HD - 1)) >> 1;
                bool rope = col < V_OFF;
                #pragma unroll
                for (int half = 0; half < 2; half++) {
                    int r = row + half * 8;
                    float v0 = acc[am][bn][2 * half], v1 = acc[am][bn][2 * half + 1];
                    if (rope) {
                        float c = cs[r * 64 + i], si = sn[r * 64 + i];
                        float t0 = v0 * c - v1 * si;
                        float t1 = v0 * si + v1 * c;
                        v0 = t0; v1 = t1;
                    }
                    uint32_t hb, lb;
                    pack_hl_f16(v0, v1, hb, lb);
                    *(uint32_t*)&Oh[(size_t)r * ldc + col] = hb;
                    *(uint32_t*)&Ol[(size_t)r * ldc + col] = lb;
                }
            }
        }
    }
}

// ---------------- tensor-core flash attention (fp16, causal, GQA 4:1) ----------------
// QK^T: Qh*Kh + Ql*Kh + Qh*Kl (fp16x3, drops 2^-22 term)
// PV:   Ph*Vh + Ph*Vl  (P single fp16)
#define ATT_SMEM (192 * 1024)

__global__ __launch_bounds__(256, 1) void attn_mma(
    const __half* __restrict__ qh_g, const __half* __restrict__ ql_g,
    __half* __restrict__ ah_g)
{
    extern __shared__ __align__(1024) char smb[];
    const uint32_t sb = smem_u32(smb);
    const uint32_t sQh = sb, sQl = sb + 32 * 1024;
    // stage: Kh +0, Kl +16K, Vh +32K, Vl +48K

    const int tid = threadIdx.x, lane = tid & 31, wid = tid >> 5;
    const int qt = (int)gridDim.x - 1 - (int)blockIdx.x;
    const int h = blockIdx.y, kvh = h >> 2;
    const int q0 = qt * 128;
    const int wq = wid * 16;

    #pragma unroll
    for (int i = 0; i < 8; i++) {
        int ch = tid + i * 256;
        int row = ch >> 4, c16 = ch & 15;
        uint32_t so = (uint32_t)(row * 256) + (uint32_t)((c16 ^ (row & 7)) << 4);
        size_t g = (size_t)(q0 + row) * QKV_N + h * HD + c16 * 8;
        cp16(sQh + so, qh_g + g);
        cp16(sQl + so, ql_g + g);
    }
    cp_commit();

    const int ktmax = 2 * qt + 1;
    auto load_kv = [&](int kt) {
        const uint32_t st = sb + 64 * 1024 + (uint32_t)(kt & 1) * 64 * 1024;
        const int k0 = kt * 64;
        #pragma unroll
        for (int i = 0; i < 4; i++) {
            int ch = tid + i * 256;
            int row = ch >> 4, c16 = ch & 15;
            uint32_t so = (uint32_t)(row * 256) + (uint32_t)((c16 ^ (row & 7)) << 4);
            size_t kb = (size_t)(k0 + row) * QKV_N + kvh * HD + c16 * 8;
            cp16(st + so,             qh_g + kb + K_OFF);
            cp16(st + 16 * 1024 + so, ql_g + kb + K_OFF);
            cp16(st + 32 * 1024 + so, qh_g + kb + V_OFF);
            cp16(st + 48 * 1024 + so, ql_g + kb + V_OFF);
        }
        cp_commit();
    };
    load_kv(0);

    float oacc[16][4];
    #pragma unroll
    for (int a = 0; a < 16; a++)
        #pragma unroll
        for (int q = 0; q < 4; q++) oacc[a][q] = 0.f;
    float m0 = -1e30f, m1 = -1e30f, l0 = 0.f, l1 = 0.f;
    const float kscale = 0.08838834764831845f * 1.44269504088896f;

    const int rin = lane & 7, grp = lane >> 3;
    const int arow = wq + rin + (grp & 1) * 8;
    const int r0 = lane >> 2;

    for (int kt = 0; kt <= ktmax; kt++) {
        if (kt < ktmax) { load_kv(kt + 1); cp_wait<1>(); }
        else            { cp_wait<0>(); }
        __syncthreads();

        const bool skip = (kt * 64) > (q0 + wq + 15);
        if (!skip) {
            const uint32_t st = sb + 64 * 1024 + (uint32_t)(kt & 1) * 64 * 1024;

            float sc[8][4];
            #pragma unroll
            for (int a = 0; a < 8; a++)
                #pragma unroll
                for (int q = 0; q < 4; q++) sc[a][q] = 0.f;

            // QK^T fp16x3
            #pragma unroll
            for (int k16 = 0; k16 < 8; k16++) {
                const int c16 = k16 * 2 + (grp >> 1);
                uint32_t aoff = (uint32_t)(arow * 256) + (uint32_t)((c16 ^ (arow & 7)) << 4);
                uint32_t aqh[4], aql[4];
                ldm_x4(aqh, sQh + aoff);
                ldm_x4(aql, sQl + aoff);
                #pragma unroll
                for (int bp = 0; bp < 2; bp++) {
                    uint32_t bh[2][4], bl[2][4];
                    #pragma unroll
                    for (int t = 0; t < 2; t++) {
                        int brow = (bp * 2 + t) * 16 + rin + (grp & 1) * 8;
                        uint32_t boff = (uint32_t)(brow * 256) + (uint32_t)((c16 ^ (brow & 7)) << 4);
                        ldm_x4(bh[t], st + boff);
                        ldm_x4(bl[t], st + 16 * 1024 + boff);
                    }
                    #pragma unroll
                    for (int t = 0; t < 2; t++) {
                        int b = bp * 2 + t;
                        mma_f16(sc[2 * b],     aqh, bh[t][0], bh[t][2]);
                        mma_f16(sc[2 * b + 1], aqh, bh[t][1], bh[t][3]);
                    }
                    #pragma unroll
                    for (int t = 0; t < 2; t++) {
                        int b = bp * 2 + t;
                        mma_f16(sc[2 * b],     aql, bh[t][0], bh[t][2]);
                        mma_f16(sc[2 * b + 1], aql, bh[t][1], bh[t][3]);
                    }
                    #pragma unroll
                    for (int t = 0; t < 2; t++) {
                        int b = bp * 2 + t;
                        mma_f16(sc[2 * b],     aqh, bl[t][0], bl[t][2]);
                        mma_f16(sc[2 * b + 1], aqh, bl[t][1], bl[t][3]);
                    }
                }
            }

            if (kt * 64 + 63 > q0 + wq) {
                int qr0 = q0 + wq + r0, qr1 = qr0 + 8;
                int cb = kt * 64 + 2 * (lane & 3);
                #pragma unroll
                for (int a = 0; a < 8; a++) {
                    int c0 = cb + a * 8, c1 = c0 + 1;
                    if (c0 > qr0) sc[a][0] = -1e30f;
                    if (c1 > qr0) sc[a][1] = -1e30f;
                    if (c0 > qr1) sc[a][2] = -1e30f;
                    if (c1 > qr1) sc[a][3] = -1e30f;
                }
            }

            float mx0 = -1e30f, mx1 = -1e30f;
            #pragma unroll
            for (int a = 0; a < 8; a++) {
                mx0 = fmaxf(mx0, fmaxf(sc[a][0], sc[a][1]));
                mx1 = fmaxf(mx1, fmaxf(sc[a][2], sc[a][3]));
            }
            mx0 = fmaxf(mx0, __shfl_xor_sync(0xffffffffu, mx0, 1));
            mx0 = fmaxf(mx0, __shfl_xor_sync(0xffffffffu, mx0, 2));
            mx1 = fmaxf(mx1, __shfl_xor_sync(0xffffffffu, mx1, 1));
            mx1 = fmaxf(mx1, __shfl_xor_sync(0xffffffffu, mx1, 2));
            float nm0 = fmaxf(m0, mx0), nm1 = fmaxf(m1, mx1);
            float corr0 = exp2f((m0 - nm0) * kscale);
            float corr1 = exp2f((m1 - nm1) * kscale);
            float s0 = 0.f, s1 = 0.f;
            #pragma unroll
            for (int a = 0; a < 8; a++) {
                sc[a][0] = exp2f((sc[a][0] - nm0) * kscale);
                sc[a][1] = exp2f((sc[a][1] - nm0) * kscale);
                sc[a][2] = exp2f((sc[a][2] - nm1) * kscale);
                sc[a][3] = exp2f((sc[a][3] - nm1) * kscale);
                s0 += sc[a][0] + sc[a][1];
                s1 += sc[a][2] + sc[a][3];
            }
            s0 += __shfl_xor_sync(0xffffffffu, s0, 1);
            s0 += __shfl_xor_sync(0xffffffffu, s0, 2);
            s1 += __shfl_xor_sync(0xffffffffu, s1, 1);
            s1 += __shfl_xor_sync(0xffffffffu, s1, 2);
            l0 = l0 * corr0 + s0;
            l1 = l1 * corr1 + s1;
            m0 = nm0; m1 = nm1;
            #pragma unroll
            for (int a = 0; a < 16; a++) {
                oacc[a][0] *= corr0; oacc[a][1] *= corr0;
                oacc[a][2] *= corr1; oacc[a][3] *= corr1;
            }

            // PV: P (fp16) x (Vh + Vl) -> 2 terms
            #pragma unroll
            for (int t = 0; t < 4; t++) {
                uint32_t ph[4];
                ph[0] = pack_f16(sc[2 * t][0],     sc[2 * t][1]);
                ph[1] = pack_f16(sc[2 * t][2],     sc[2 * t][3]);
                ph[2] = pack_f16(sc[2 * t + 1][0], sc[2 * t + 1][1]);
                ph[3] = pack_f16(sc[2 * t + 1][2], sc[2 * t + 1][3]);
                #pragma unroll
                for (int dp = 0; dp < 4; dp++) {
                    uint32_t vh[2][4], vl[2][4];
                    #pragma unroll
                    for (int u = 0; u < 2; u++) {
                        int d = dp * 2 + u;
                        int vrow = t * 16 + (grp & 1) * 8 + rin;
                        int c16 = d * 2 + (grp >> 1);
                        uint32_t voff = (uint32_t)(vrow * 256) + (uint32_t)((c16 ^ (vrow & 7)) << 4);
                        ldm_x4t(vh[u], st + 32 * 1024 + voff);
                        ldm_x4t(vl[u], st + 48 * 1024 + voff);
                    }
                    #pragma unroll
                    for (int u = 0; u < 2; u++) {
                        int d = dp * 2 + u;
                        mma_f16(oacc[2 * d],     ph, vh[u][0], vh[u][1]);
                        mma_f16(oacc[2 * d + 1], ph, vh[u][2], vh[u][3]);
                    }
                    #pragma unroll
                    for (int u = 0; u < 2; u++) {
                        int d = dp * 2 + u;
                        mma_f16(oacc[2 * d],     ph, vl[u][0], vl[u][1]);
                        mma_f16(oacc[2 * d + 1], ph, vl[u][2], vl[u][3]);
                    }
                }
            }
        }
        __syncthreads();
    }

    // epilogue: normalize, write fp16 hi only (1-term out-proj)
    float inv0 = 1.f / l0, inv1 = 1.f / l1;
    int gr0 = q0 + wq + r0, gr1 = gr0 + 8;
    #pragma unroll
    for (int a = 0; a < 16; a++) {
        int d0 = a * 8 + 2 * (lane & 3);
        *(uint32_t*)&ah_g[(size_t)gr0 * DIM + h * HD + d0] =
            pack_f16(oacc[a][0] * inv0, oacc[a][1] * inv0);
        *(uint32_t*)&ah_g[(size_t)gr1 * DIM + h * HD + d0] =
            pack_f16(oacc[a][2] * inv1, oacc[a][3] * inv1);
    }
}

// ---------------- launch ----------------
extern "C" void kernel_launch(void* const* d_in, const int* in_sizes, int n_in,
                              void* d_out, int out_size)
{
    const float* x  = (const float*)d_in[0];
    const float* fc = (const float*)d_in[1];
    const float* fs = (const float*)d_in[2];
    const float* wq = (const float*)d_in[5];
    const float* wk = (const float*)d_in[6];
    const float* wv = (const float*)d_in[7];
    const float* wo = (const float*)d_in[8];
    float* out = (float*)d_out;

    __half *qh, *ql, *xh, *xl, *wh, *oh, *ah;
    cudaGetSymbolAddress((void**)&qh, g_qh);  cudaGetSymbolAddress((void**)&ql, g_ql);
    cudaGetSymbolAddress((void**)&xh, g_xh);  cudaGetSymbolAddress((void**)&xl, g_xl);
    cudaGetSymbolAddress((void**)&wh, g_wh);  cudaGetSymbolAddress((void**)&oh, g_oh);
    cudaGetSymbolAddress((void**)&ah, g_ah);

    cudaFuncSetAttribute(gemm_f16, cudaFuncAttributeMaxDynamicSharedMemorySize, GEMM_SMEM);
    cudaFuncSetAttribute(attn_mma, cudaFuncAttributeMaxDynamicSharedMemorySize, ATT_SMEM);

    dim3 blk(256);
    int n4x = S * DIM / 4;
    split_f16hl<<<(n4x + 255) / 256, blk>>>(x, xh, xl, n4x);
    int n4q = DIM * DIM / 4;
    split_f16h<<<(n4q + 255) / 256, blk>>>(wq, wh, n4q);
    int n4k = 1024 * DIM / 4;
    split_f16h<<<(n4k + 255) / 256, blk>>>(wk, wh + (size_t)4096 * DIM, n4k);
    split_f16h<<<(n4k + 255) / 256, blk>>>(wv, wh + (size_t)5120 * DIM, n4k);
    split_f16h<<<(n4q + 255) / 256, blk>>>(wo, oh, n4q);

    // QKV projection (fp16 2-term) with fused RoPE + fp16 hi/lo split epilogue
    gemm_f16<<<dim3(S / 128, QKV_N / 256), blk, GEMM_SMEM>>>(
        xh, xl, wh, nullptr, DIM, QKV_N, 1, 2, fc, fs, qh, ql);

    // tensor-core attention (fp16) -> fp16 hi output
    attn_mma<<<dim3(S / 128, NH), blk, ATT_SMEM>>>(qh, ql, ah);

    // output projection (fp16 1-term) -> fp32 out
    gemm_f16<<<dim3(S / 128, DIM / 256), blk, GEMM_SMEM>>>(
        ah, nullptr, oh, out, DIM, DIM, 0, 1, nullptr, nullptr, nullptr, nullptr);
}

// round 10
// speedup vs baseline: 1.8235x; 1.2238x over previous
#include <cuda_runtime.h>
#include <cuda_bf16.h>
#include <cuda_fp16.h>
#include <cstdint>

// ---------------- problem constants ----------------
#define S       2048
#define DIM     4096
#define NH      32
#define HD      128
#define QKV_N   6144
#define K_OFF   4096
#define V_OFF   5120

// ---------------- scratch (device globals) ----------------
__device__ __half g_qh[S * QKV_N], g_ql[S * QKV_N];   // rope'd qkv, fp16 hi/lo
__device__ __half g_xh[S * DIM];                      // x fp16 hi
__device__ __half g_wh[QKV_N * DIM];                  // packed wq|wk|wv fp16 hi
__device__ __half g_oh[DIM * DIM];                    // wo fp16 hi
__device__ __half g_ah[S * DIM];                      // attention out fp16 hi

// ---------------- helpers ----------------
__device__ __forceinline__ uint32_t smem_u32(const void* p) {
    uint32_t a;
    asm("{ .reg .u64 t; cvta.to.shared.u64 t, %1; cvt.u32.u64 %0, t; }" : "=r"(a) : "l"(p));
    return a;
}
__device__ __forceinline__ void cp16(uint32_t dst, const void* src) {
    asm volatile("cp.async.cg.shared.global [%0], [%1], 16;" :: "r"(dst), "l"(src));
}
__device__ __forceinline__ void cp_commit() {
    asm volatile("cp.async.commit_group;");
}
template <int N>
__device__ __forceinline__ void cp_wait() {
    asm volatile("cp.async.wait_group %0;" :: "n"(N));
}
__device__ __forceinline__ void ldm_x4(uint32_t* r, uint32_t addr) {
    asm volatile("ldmatrix.sync.aligned.m8n8.x4.shared.b16 {%0,%1,%2,%3}, [%4];"
                 : "=r"(r[0]), "=r"(r[1]), "=r"(r[2]), "=r"(r[3]) : "r"(addr));
}
__device__ __forceinline__ void ldm_x4t(uint32_t* r, uint32_t addr) {
    asm volatile("ldmatrix.sync.aligned.m8n8.x4.trans.shared.b16 {%0,%1,%2,%3}, [%4];"
                 : "=r"(r[0]), "=r"(r[1]), "=r"(r[2]), "=r"(r[3]) : "r"(addr));
}
__device__ __forceinline__ void mma_f16(float* c, const uint32_t* a, uint32_t b0, uint32_t b1) {
    asm volatile(
        "mma.sync.aligned.m16n8k16.row.col.f32.f16.f16.f32 "
        "{%0,%1,%2,%3}, {%4,%5,%6,%7}, {%8,%9}, {%0,%1,%2,%3};"
        : "+f"(c[0]), "+f"(c[1]), "+f"(c[2]), "+f"(c[3])
        : "r"(a[0]), "r"(a[1]), "r"(a[2]), "r"(a[3]), "r"(b0), "r"(b1));
}
__device__ __forceinline__ void pack_hl_f16(float x, float y, uint32_t& h, uint32_t& l) {
    __half2 hb = __floats2half2_rn(x, y);
    float hx = __low2float(hb), hy = __high2float(hb);
    __half2 lb = __floats2half2_rn(x - hx, y - hy);
    h = *reinterpret_cast<uint32_t*>(&hb);
    l = *reinterpret_cast<uint32_t*>(&lb);
}
__device__ __forceinline__ uint32_t pack_f16(float x, float y) {
    __half2 hb = __floats2half2_rn(x, y);
    return *reinterpret_cast<uint32_t*>(&hb);
}

// ---------------- splits ----------------
__global__ void split_f16h(const float* __restrict__ src, __half* __restrict__ hi, int n4)
{
    int i = blockIdx.x * blockDim.x + threadIdx.x;
    if (i >= n4) return;
    float4 v = ((const float4*)src)[i];
    ((__half2*)hi)[2 * i]     = __floats2half2_rn(v.x, v.y);
    ((__half2*)hi)[2 * i + 1] = __floats2half2_rn(v.z, v.w);
}

// ---------------- fp16 GEMM, CTA 128x256, warp 64x64, 3-stage pipeline ----------------
// terms==2: C = Ah*Bh + Al*Bh ; terms==1: C = Ah*Bh
// mode 0: write fp32 C; mode 1: RoPE (cols < V_OFF) + fp16 hi/lo split into Oh/Ol
#define A_HI 0
#define A_LO (16 * 1024)
#define B_HI (32 * 1024)
#define STG_B (64 * 1024)
#define GEMM_SMEM (3 * STG_B)

__global__ __launch_bounds__(256, 1) void gemm_f16(
    const __half* __restrict__ Ah, const __half* __restrict__ Al,
    const __half* __restrict__ Bh,
    float* __restrict__ C, int K, int ldc, int mode, int terms,
    const float* __restrict__ cs, const float* __restrict__ sn,
    __half* __restrict__ Oh, __half* __restrict__ Ol)
{
    extern __shared__ __align__(1024) char smc[];
    const uint32_t sbase = smem_u32(smc);

    const int tid  = threadIdx.x;
    const int lane = tid & 31;
    const int wid  = tid >> 5;
    const int wm   = wid & 1;
    const int wn   = wid >> 1;
    const int m0 = blockIdx.x * 128;
    const int n0 = blockIdx.y * 256;

    const int grp = lane >> 3;
    const int rin = lane & 7;

    float acc[4][8][4];
    #pragma unroll
    for (int i = 0; i < 4; i++)
        #pragma unroll
        for (int j = 0; j < 8; j++)
            #pragma unroll
            for (int q = 0; q < 4; q++) acc[i][j][q] = 0.f;

    const int nk = K >> 6;

    auto load_chunk = [&](int it) {
        const int k0 = it << 6;
        const uint32_t sb = sbase + (uint32_t)(it % 3) * STG_B;
        #pragma unroll
        for (int i = 0; i < 4; i++) {
            int id = tid + i * 256;
            int row = id >> 3, c16 = id & 7;
            uint32_t so = (uint32_t)(row * 128) + ((uint32_t)(c16 ^ (row & 7)) << 4);
            size_t g = (size_t)(m0 + row) * K + k0 + c16 * 8;
            cp16(sb + A_HI + so, Ah + g);
            if (terms == 2) cp16(sb + A_LO + so, Al + g);
        }
        #pragma unroll
        for (int i = 0; i < 8; i++) {
            int id = tid + i * 256;
            int row = id >> 3, c16 = id & 7;
            uint32_t so = (uint32_t)(row * 128) + ((uint32_t)(c16 ^ (row & 7)) << 4);
            size_t g = (size_t)(n0 + row) * K + k0 + c16 * 8;
            cp16(sb + B_HI + so, Bh + g);
        }
        cp_commit();
    };

    load_chunk(0);
    if (nk > 1) load_chunk(1); else cp_commit();

    for (int it = 0; it < nk; it++) {
        if (it + 2 < nk) load_chunk(it + 2); else cp_commit();
        cp_wait<2>();
        __syncthreads();

        const uint32_t sA = sbase + (uint32_t)(it % 3) * STG_B;
        const uint32_t sB = sA + B_HI;
        #pragma unroll
        for (int kc = 0; kc < 4; kc++) {
            const int c16 = kc * 2 + (grp >> 1);

            uint32_t ah[4][4], al[4][4];
            #pragma unroll
            for (int am = 0; am < 4; am++) {
                int row = wm * 64 + am * 16 + rin + (grp & 1) * 8;
                uint32_t so = (uint32_t)(row * 128) + ((uint32_t)(c16 ^ (row & 7)) << 4);
                ldm_x4(ah[am], sA + so);
                if (terms == 2) ldm_x4(al[am], sA + A_LO + so);
            }

            #pragma unroll
            for (int bt = 0; bt < 4; bt++) {
                int row = wn * 64 + bt * 16 + rin + (grp & 1) * 8;
                uint32_t so = (uint32_t)(row * 128) + ((uint32_t)(c16 ^ (row & 7)) << 4);
                uint32_t bh[4];
                ldm_x4(bh, sB + so);
                #pragma unroll
                for (int am = 0; am < 4; am++) {
                    mma_f16(acc[am][2 * bt],     ah[am], bh[0], bh[2]);
                    mma_f16(acc[am][2 * bt + 1], ah[am], bh[1], bh[3]);
                }
                if (terms == 2) {
                    #pragma unroll
                    for (int am = 0; am < 4; am++) {
                        mma_f16(acc[am][2 * bt],     al[am], bh[0], bh[2]);
                        mma_f16(acc[am][2 * bt + 1], al[am], bh[1], bh[3]);
                    }
                }
            }
        }
        __syncthreads();
    }

    if (mode == 0) {
        #pragma unroll
        for (int am = 0; am < 4; am++) {
            int row = m0 + wm * 64 + am * 16 + (lane >> 2);
            #pragma unroll
            for (int bn = 0; bn < 8; bn++) {
                int col = n0 + wn * 64 + bn * 8 + (lane & 3) * 2;
                *(float2*)&C[(size_t)row * ldc + col]       = make_float2(acc[am][bn][0], acc[am][bn][1]);
                *(float2*)&C[(size_t)(row + 8) * ldc + col] = make_float2(acc[am][bn][2], acc[am][bn][3]);
            }
        }
    } else {
        // RoPE (cols < V_OFF) + fp16 hi/lo split -> Oh/Ol
        #pragma unroll
        for (int am = 0; am < 4; am++) {
            int row = m0 + wm * 64 + am * 16 + (lane >> 2);
            #pragma unroll
            for (int bn = 0; bn < 8; bn++) {
                int col = n0 + wn * 64 + bn * 8 + (lane & 3) * 2;
                int i = (col & (HD - 1)) >> 1;
                bool rope = col < V_OFF;
                #pragma unroll
                for (int half = 0; half < 2; half++) {
                    int r = row + half * 8;
                    float v0 = acc[am][bn][2 * half], v1 = acc[am][bn][2 * half + 1];
                    if (rope) {
                        float c = cs[r * 64 + i], si = sn[r * 64 + i];
                        float t0 = v0 * c - v1 * si;
                        float t1 = v0 * si + v1 * c;
                        v0 = t0; v1 = t1;
                    }
                    uint32_t hb, lb;
                    pack_hl_f16(v0, v1, hb, lb);
                    *(uint32_t*)&Oh[(size_t)r * ldc + col] = hb;
                    *(uint32_t*)&Ol[(size_t)r * ldc + col] = lb;
                }
            }
        }
    }
}

// ---------------- tensor-core flash attention (fp16, causal, GQA 4:1) ----------------
// QK^T: Qh*Kh + Ql*Kh + Qh*Kl ; PV: Ph*Vh + Ph*Vl
#define ATT_SMEM (192 * 1024)

__global__ __launch_bounds__(256, 1) void attn_mma(
    const __half* __restrict__ qh_g, const __half* __restrict__ ql_g,
    __half* __restrict__ ah_g)
{
    extern __shared__ __align__(1024) char smb[];
    const uint32_t sb = smem_u32(smb);
    const uint32_t sQh = sb, sQl = sb + 32 * 1024;

    const int tid = threadIdx.x, lane = tid & 31, wid = tid >> 5;
    const int qt = (int)gridDim.x - 1 - (int)blockIdx.x;
    const int h = blockIdx.y, kvh = h >> 2;
    const int q0 = qt * 128;
    const int wq = wid * 16;

    #pragma unroll
    for (int i = 0; i < 8; i++) {
        int ch = tid + i * 256;
        int row = ch >> 4, c16 = ch & 15;
        uint32_t so = (uint32_t)(row * 256) + (uint32_t)((c16 ^ (row & 7)) << 4);
        size_t g = (size_t)(q0 + row) * QKV_N + h * HD + c16 * 8;
        cp16(sQh + so, qh_g + g);
        cp16(sQl + so, ql_g + g);
    }
    cp_commit();

    const int ktmax = 2 * qt + 1;
    auto load_kv = [&](int kt) {
        const uint32_t st = sb + 64 * 1024 + (uint32_t)(kt & 1) * 64 * 1024;
        const int k0 = kt * 64;
        #pragma unroll
        for (int i = 0; i < 4; i++) {
            int ch = tid + i * 256;
            int row = ch >> 4, c16 = ch & 15;
            uint32_t so = (uint32_t)(row * 256) + (uint32_t)((c16 ^ (row & 7)) << 4);
            size_t kb = (size_t)(k0 + row) * QKV_N + kvh * HD + c16 * 8;
            cp16(st + so,             qh_g + kb + K_OFF);
            cp16(st + 16 * 1024 + so, ql_g + kb + K_OFF);
            cp16(st + 32 * 1024 + so, qh_g + kb + V_OFF);
            cp16(st + 48 * 1024 + so, ql_g + kb + V_OFF);
        }
        cp_commit();
    };
    load_kv(0);

    float oacc[16][4];
    #pragma unroll
    for (int a = 0; a < 16; a++)
        #pragma unroll
        for (int q = 0; q < 4; q++) oacc[a][q] = 0.f;
    float m0 = -1e30f, m1 = -1e30f, l0 = 0.f, l1 = 0.f;
    const float kscale = 0.08838834764831845f * 1.44269504088896f;

    const int rin = lane & 7, grp = lane >> 3;
    const int arow = wq + rin + (grp & 1) * 8;
    const int r0 = lane >> 2;

    for (int kt = 0; kt <= ktmax; kt++) {
        if (kt < ktmax) { load_kv(kt + 1); cp_wait<1>(); }
        else            { cp_wait<0>(); }
        __syncthreads();

        const bool skip = (kt * 64) > (q0 + wq + 15);
        if (!skip) {
            const uint32_t st = sb + 64 * 1024 + (uint32_t)(kt & 1) * 64 * 1024;

            float sc[8][4];
            #pragma unroll
            for (int a = 0; a < 8; a++)
                #pragma unroll
                for (int q = 0; q < 4; q++) sc[a][q] = 0.f;

            #pragma unroll
            for (int k16 = 0; k16 < 8; k16++) {
                const int c16 = k16 * 2 + (grp >> 1);
                uint32_t aoff = (uint32_t)(arow * 256) + (uint32_t)((c16 ^ (arow & 7)) << 4);
                uint32_t aqh[4], aql[4];
                ldm_x4(aqh, sQh + aoff);
                ldm_x4(aql, sQl + aoff);
                #pragma unroll
                for (int bp = 0; bp < 2; bp++) {
                    uint32_t bh[2][4], bl[2][4];
                    #pragma unroll
                    for (int t = 0; t < 2; t++) {
                        int brow = (bp * 2 + t) * 16 + rin + (grp & 1) * 8;
                        uint32_t boff = (uint32_t)(brow * 256) + (uint32_t)((c16 ^ (brow & 7)) << 4);
                        ldm_x4(bh[t], st + boff);
                        ldm_x4(bl[t], st + 16 * 1024 + boff);
                    }
                    #pragma unroll
                    for (int t = 0; t < 2; t++) {
                        int b = bp * 2 + t;
                        mma_f16(sc[2 * b],     aqh, bh[t][0], bh[t][2]);
                        mma_f16(sc[2 * b + 1], aqh, bh[t][1], bh[t][3]);
                    }
                    #pragma unroll
                    for (int t = 0; t < 2; t++) {
                        int b = bp * 2 + t;
                        mma_f16(sc[2 * b],     aql, bh[t][0], bh[t][2]);
                        mma_f16(sc[2 * b + 1], aql, bh[t][1], bh[t][3]);
                    }
                    #pragma unroll
                    for (int t = 0; t < 2; t++) {
                        int b = bp * 2 + t;
                        mma_f16(sc[2 * b],     aqh, bl[t][0], bl[t][2]);
                        mma_f16(sc[2 * b + 1], aqh, bl[t][1], bl[t][3]);
                    }
                }
            }

            if (kt * 64 + 63 > q0 + wq) {
                int qr0 = q0 + wq + r0, qr1 = qr0 + 8;
                int cb = kt * 64 + 2 * (lane & 3);
                #pragma unroll
                for (int a = 0; a < 8; a++) {
                    int c0 = cb + a * 8, c1 = c0 + 1;
                    if (c0 > qr0) sc[a][0] = -1e30f;
                    if (c1 > qr0) sc[a][1] = -1e30f;
                    if (c0 > qr1) sc[a][2] = -1e30f;
                    if (c1 > qr1) sc[a][3] = -1e30f;
                }
            }

            float mx0 = -1e30f, mx1 = -1e30f;
            #pragma unroll
            for (int a = 0; a < 8; a++) {
                mx0 = fmaxf(mx0, fmaxf(sc[a][0], sc[a][1]));
                mx1 = fmaxf(mx1, fmaxf(sc[a][2], sc[a][3]));
            }
            mx0 = fmaxf(mx0, __shfl_xor_sync(0xffffffffu, mx0, 1));
            mx0 = fmaxf(mx0, __shfl_xor_sync(0xffffffffu, mx0, 2));
            mx1 = fmaxf(mx1, __shfl_xor_sync(0xffffffffu, mx1, 1));
            mx1 = fmaxf(mx1, __shfl_xor_sync(0xffffffffu, mx1, 2));
            float nm0 = fmaxf(m0, mx0), nm1 = fmaxf(m1, mx1);
            float corr0 = exp2f((m0 - nm0) * kscale);
            float corr1 = exp2f((m1 - nm1) * kscale);
            float s0 = 0.f, s1 = 0.f;
            #pragma unroll
            for (int a = 0; a < 8; a++) {
                sc[a][0] = exp2f((sc[a][0] - nm0) * kscale);
                sc[a][1] = exp2f((sc[a][1] - nm0) * kscale);
                sc[a][2] = exp2f((sc[a][2] - nm1) * kscale);
                sc[a][3] = exp2f((sc[a][3] - nm1) * kscale);
                s0 += sc[a][0] + sc[a][1];
                s1 += sc[a][2] + sc[a][3];
            }
            s0 += __shfl_xor_sync(0xffffffffu, s0, 1);
            s0 += __shfl_xor_sync(0xffffffffu, s0, 2);
            s1 += __shfl_xor_sync(0xffffffffu, s1, 1);
            s1 += __shfl_xor_sync(0xffffffffu, s1, 2);
            l0 = l0 * corr0 + s0;
            l1 = l1 * corr1 + s1;
            m0 = nm0; m1 = nm1;
            #pragma unroll
            for (int a = 0; a < 16; a++) {
                oacc[a][0] *= corr0; oacc[a][1] *= corr0;
                oacc[a][2] *= corr1; oacc[a][3] *= corr1;
            }

            #pragma unroll
            for (int t = 0; t < 4; t++) {
                uint32_t ph[4];
                ph[0] = pack_f16(sc[2 * t][0],     sc[2 * t][1]);
                ph[1] = pack_f16(sc[2 * t][2],     sc[2 * t][3]);
                ph[2] = pack_f16(sc[2 * t + 1][0], sc[2 * t + 1][1]);
                ph[3] = pack_f16(sc[2 * t + 1][2], sc[2 * t + 1][3]);
                #pragma unroll
                for (int dp = 0; dp < 4; dp++) {
                    uint32_t vh[2][4], vl[2][4];
                    #pragma unroll
                    for (int u = 0; u < 2; u++) {
                        int d = dp * 2 + u;
                        int vrow = t * 16 + (grp & 1) * 8 + rin;
                        int c16 = d * 2 + (grp >> 1);
                        uint32_t voff = (uint32_t)(vrow * 256) + (uint32_t)((c16 ^ (vrow & 7)) << 4);
                        ldm_x4t(vh[u], st + 32 * 1024 + voff);
                        ldm_x4t(vl[u], st + 48 * 1024 + voff);
                    }
                    #pragma unroll
                    for (int u = 0; u < 2; u++) {
                        int d = dp * 2 + u;
                        mma_f16(oacc[2 * d],     ph, vh[u][0], vh[u][1]);
                        mma_f16(oacc[2 * d + 1], ph, vh[u][2], vh[u][3]);
                    }
                    #pragma unroll
                    for (int u = 0; u < 2; u++) {
                        int d = dp * 2 + u;
                        mma_f16(oacc[2 * d],     ph, vl[u][0], vl[u][1]);
                        mma_f16(oacc[2 * d + 1], ph, vl[u][2], vl[u][3]);
                    }
                }
            }
        }
        __syncthreads();
    }

    float inv0 = 1.f / l0, inv1 = 1.f / l1;
    int gr0 = q0 + wq + r0, gr1 = gr0 + 8;
    #pragma unroll
    for (int a = 0; a < 16; a++) {
        int d0 = a * 8 + 2 * (lane & 3);
        *(uint32_t*)&ah_g[(size_t)gr0 * DIM + h * HD + d0] =
            pack_f16(oacc[a][0] * inv0, oacc[a][1] * inv0);
        *(uint32_t*)&ah_g[(size_t)gr1 * DIM + h * HD + d0] =
            pack_f16(oacc[a][2] * inv1, oacc[a][3] * inv1);
    }
}

// ---------------- launch ----------------
extern "C" void kernel_launch(void* const* d_in, const int* in_sizes, int n_in,
                              void* d_out, int out_size)
{
    const float* x  = (const float*)d_in[0];
    const float* fc = (const float*)d_in[1];
    const float* fs = (const float*)d_in[2];
    const float* wq = (const float*)d_in[5];
    const float* wk = (const float*)d_in[6];
    const float* wv = (const float*)d_in[7];
    const float* wo = (const float*)d_in[8];
    float* out = (float*)d_out;

    __half *qh, *ql, *xh, *wh, *oh, *ah;
    cudaGetSymbolAddress((void**)&qh, g_qh);  cudaGetSymbolAddress((void**)&ql, g_ql);
    cudaGetSymbolAddress((void**)&xh, g_xh);
    cudaGetSymbolAddress((void**)&wh, g_wh);  cudaGetSymbolAddress((void**)&oh, g_oh);
    cudaGetSymbolAddress((void**)&ah, g_ah);

    cudaFuncSetAttribute(gemm_f16, cudaFuncAttributeMaxDynamicSharedMemorySize, GEMM_SMEM);
    cudaFuncSetAttribute(attn_mma, cudaFuncAttributeMaxDynamicSharedMemorySize, ATT_SMEM);

    dim3 blk(256);
    int n4x = S * DIM / 4;
    split_f16h<<<(n4x + 255) / 256, blk>>>(x, xh, n4x);
    int n4q = DIM * DIM / 4;
    split_f16h<<<(n4q + 255) / 256, blk>>>(wq, wh, n4q);
    int n4k = 1024 * DIM / 4;
    split_f16h<<<(n4k + 255) / 256, blk>>>(wk, wh + (size_t)4096 * DIM, n4k);
    split_f16h<<<(n4k + 255) / 256, blk>>>(wv, wh + (size_t)5120 * DIM, n4k);
    split_f16h<<<(n4q + 255) / 256, blk>>>(wo, oh, n4q);

    // QKV projection (fp16 1-term) with fused RoPE + fp16 hi/lo split epilogue
    gemm_f16<<<dim3(S / 128, QKV_N / 256), blk, GEMM_SMEM>>>(
        xh, nullptr, wh, nullptr, DIM, QKV_N, 1, 1, fc, fs, qh, ql);

    // tensor-core attention (fp16) -> fp16 hi output
    attn_mma<<<dim3(S / 128, NH), blk, ATT_SMEM>>>(qh, ql, ah);

    // output projection (fp16 1-term) -> fp32 out
    gemm_f16<<<dim3(S / 128, DIM / 256), blk, GEMM_SMEM>>>(
        ah, nullptr, oh, out, DIM, DIM, 0, 1, nullptr, nullptr, nullptr, nullptr);
}

// round 11
// speedup vs baseline: 2.0140x; 1.1044x over previous
#include <cuda_runtime.h>
#include <cuda_bf16.h>
#include <cuda_fp16.h>
#include <cstdint>

// ---------------- problem constants ----------------
#define S       2048
#define DIM     4096
#define NH      32
#define HD      128
#define QKV_N   6144
#define K_OFF   4096
#define V_OFF   5120

// ---------------- scratch (device globals) ----------------
__device__ __half g_qh[S * QKV_N], g_ql[S * QKV_N];   // rope'd qkv, fp16 hi/lo
__device__ __half g_xh[S * DIM];                      // x fp16 hi
__device__ __half g_wh[QKV_N * DIM];                  // packed wq|wk|wv fp16 hi
__device__ __half g_oh[DIM * DIM];                    // wo fp16 hi
__device__ __half g_ah[S * DIM];                      // attention out fp16 hi

// ---------------- helpers ----------------
__device__ __forceinline__ uint32_t smem_u32(const void* p) {
    uint32_t a;
    asm("{ .reg .u64 t; cvta.to.shared.u64 t, %1; cvt.u32.u64 %0, t; }" : "=r"(a) : "l"(p));
    return a;
}
__device__ __forceinline__ void cp16(uint32_t dst, const void* src) {
    asm volatile("cp.async.cg.shared.global [%0], [%1], 16;" :: "r"(dst), "l"(src));
}
__device__ __forceinline__ void cp_commit() {
    asm volatile("cp.async.commit_group;");
}
template <int N>
__device__ __forceinline__ void cp_wait() {
    asm volatile("cp.async.wait_group %0;" :: "n"(N));
}
__device__ __forceinline__ void ldm_x4(uint32_t* r, uint32_t addr) {
    asm volatile("ldmatrix.sync.aligned.m8n8.x4.shared.b16 {%0,%1,%2,%3}, [%4];"
                 : "=r"(r[0]), "=r"(r[1]), "=r"(r[2]), "=r"(r[3]) : "r"(addr));
}
__device__ __forceinline__ void ldm_x4t(uint32_t* r, uint32_t addr) {
    asm volatile("ldmatrix.sync.aligned.m8n8.x4.trans.shared.b16 {%0,%1,%2,%3}, [%4];"
                 : "=r"(r[0]), "=r"(r[1]), "=r"(r[2]), "=r"(r[3]) : "r"(addr));
}
__device__ __forceinline__ void mma_f16(float* c, const uint32_t* a, uint32_t b0, uint32_t b1) {
    asm volatile(
        "mma.sync.aligned.m16n8k16.row.col.f32.f16.f16.f32 "
        "{%0,%1,%2,%3}, {%4,%5,%6,%7}, {%8,%9}, {%0,%1,%2,%3};"
        : "+f"(c[0]), "+f"(c[1]), "+f"(c[2]), "+f"(c[3])
        : "r"(a[0]), "r"(a[1]), "r"(a[2]), "r"(a[3]), "r"(b0), "r"(b1));
}
__device__ __forceinline__ void pack_hl_f16(float x, float y, uint32_t& h, uint32_t& l) {
    __half2 hb = __floats2half2_rn(x, y);
    float hx = __low2float(hb), hy = __high2float(hb);
    __half2 lb = __floats2half2_rn(x - hx, y - hy);
    h = *reinterpret_cast<uint32_t*>(&hb);
    l = *reinterpret_cast<uint32_t*>(&lb);
}
__device__ __forceinline__ uint32_t pack_f16(float x, float y) {
    __half2 hb = __floats2half2_rn(x, y);
    return *reinterpret_cast<uint32_t*>(&hb);
}

// ---------------- splits ----------------
__global__ void split_f16h(const float* __restrict__ src, __half* __restrict__ hi, int n4)
{
    int i = blockIdx.x * blockDim.x + threadIdx.x;
    if (i >= n4) return;
    float4 v = ((const float4*)src)[i];
    ((__half2*)hi)[2 * i]     = __floats2half2_rn(v.x, v.y);
    ((__half2*)hi)[2 * i + 1] = __floats2half2_rn(v.z, v.w);
}

// all 4 weight matrices in one launch (range dispatch)
#define NQ4 (DIM * DIM / 4)        // 4M quads (wq / wo)
#define NK4 (1024 * DIM / 4)       // 1M quads (wk / wv)
__global__ void split_weights(const float* __restrict__ wq, const float* __restrict__ wk,
                              const float* __restrict__ wv, const float* __restrict__ wo,
                              __half* __restrict__ wh, __half* __restrict__ oh)
{
    int i = blockIdx.x * blockDim.x + threadIdx.x;
    if (i >= 2 * NQ4 + 2 * NK4) return;
    const float* src;
    __half* dst;
    int j;
    if (i < NQ4)                 { j = i;                src = wq; dst = wh; }
    else if (i < NQ4 + NK4)      { j = i - NQ4;          src = wk; dst = wh + (size_t)4096 * DIM; }
    else if (i < NQ4 + 2 * NK4)  { j = i - NQ4 - NK4;    src = wv; dst = wh + (size_t)5120 * DIM; }
    else                         { j = i - NQ4 - 2*NK4;  src = wo; dst = oh; }
    float4 v = ((const float4*)src)[j];
    ((__half2*)dst)[2 * j]     = __floats2half2_rn(v.x, v.y);
    ((__half2*)dst)[2 * j + 1] = __floats2half2_rn(v.z, v.w);
}

// ---------------- fp16 GEMM, CTA 128x256, warp 64x64, 3-stage pipeline ----------------
// terms==2: C = Ah*Bh + Al*Bh ; terms==1: C = Ah*Bh
// mode 0: write fp32 C; mode 1: RoPE (cols < V_OFF) + fp16 hi/lo split into Oh/Ol
#define A_HI 0
#define A_LO (16 * 1024)
#define B_HI (32 * 1024)
#define STG_B (64 * 1024)
#define GEMM_SMEM (3 * STG_B)

__global__ __launch_bounds__(256, 1) void gemm_f16(
    const __half* __restrict__ Ah, const __half* __restrict__ Al,
    const __half* __restrict__ Bh,
    float* __restrict__ C, int K, int ldc, int mode, int terms,
    const float* __restrict__ cs, const float* __restrict__ sn,
    __half* __restrict__ Oh, __half* __restrict__ Ol)
{
    extern __shared__ __align__(1024) char smc[];
    const uint32_t sbase = smem_u32(smc);

    const int tid  = threadIdx.x;
    const int lane = tid & 31;
    const int wid  = tid >> 5;
    const int wm   = wid & 1;
    const int wn   = wid >> 1;
    const int m0 = blockIdx.x * 128;
    const int n0 = blockIdx.y * 256;

    const int grp = lane >> 3;
    const int rin = lane & 7;

    float acc[4][8][4];
    #pragma unroll
    for (int i = 0; i < 4; i++)
        #pragma unroll
        for (int j = 0; j < 8; j++)
            #pragma unroll
            for (int q = 0; q < 4; q++) acc[i][j][q] = 0.f;

    const int nk = K >> 6;

    auto load_chunk = [&](int it) {
        const int k0 = it << 6;
        const uint32_t sb = sbase + (uint32_t)(it % 3) * STG_B;
        #pragma unroll
        for (int i = 0; i < 4; i++) {
            int id = tid + i * 256;
            int row = id >> 3, c16 = id & 7;
            uint32_t so = (uint32_t)(row * 128) + ((uint32_t)(c16 ^ (row & 7)) << 4);
            size_t g = (size_t)(m0 + row) * K + k0 + c16 * 8;
            cp16(sb + A_HI + so, Ah + g);
            if (terms == 2) cp16(sb + A_LO + so, Al + g);
        }
        #pragma unroll
        for (int i = 0; i < 8; i++) {
            int id = tid + i * 256;
            int row = id >> 3, c16 = id & 7;
            uint32_t so = (uint32_t)(row * 128) + ((uint32_t)(c16 ^ (row & 7)) << 4);
            size_t g = (size_t)(n0 + row) * K + k0 + c16 * 8;
            cp16(sb + B_HI + so, Bh + g);
        }
        cp_commit();
    };

    load_chunk(0);
    if (nk > 1) load_chunk(1); else cp_commit();

    for (int it = 0; it < nk; it++) {
        if (it + 2 < nk) load_chunk(it + 2); else cp_commit();
        cp_wait<2>();
        __syncthreads();

        const uint32_t sA = sbase + (uint32_t)(it % 3) * STG_B;
        const uint32_t sB = sA + B_HI;
        #pragma unroll
        for (int kc = 0; kc < 4; kc++) {
            const int c16 = kc * 2 + (grp >> 1);

            uint32_t ah[4][4], al[4][4];
            #pragma unroll
            for (int am = 0; am < 4; am++) {
                int row = wm * 64 + am * 16 + rin + (grp & 1) * 8;
                uint32_t so = (uint32_t)(row * 128) + ((uint32_t)(c16 ^ (row & 7)) << 4);
                ldm_x4(ah[am], sA + so);
                if (terms == 2) ldm_x4(al[am], sA + A_LO + so);
            }

            #pragma unroll
            for (int bt = 0; bt < 4; bt++) {
                int row = wn * 64 + bt * 16 + rin + (grp & 1) * 8;
                uint32_t so = (uint32_t)(row * 128) + ((uint32_t)(c16 ^ (row & 7)) << 4);
                uint32_t bh[4];
                ldm_x4(bh, sB + so);
                #pragma unroll
                for (int am = 0; am < 4; am++) {
                    mma_f16(acc[am][2 * bt],     ah[am], bh[0], bh[2]);
                    mma_f16(acc[am][2 * bt + 1], ah[am], bh[1], bh[3]);
                }
                if (terms == 2) {
                    #pragma unroll
                    for (int am = 0; am < 4; am++) {
                        mma_f16(acc[am][2 * bt],     al[am], bh[0], bh[2]);
                        mma_f16(acc[am][2 * bt + 1], al[am], bh[1], bh[3]);
                    }
                }
            }
        }
        __syncthreads();
    }

    if (mode == 0) {
        #pragma unroll
        for (int am = 0; am < 4; am++) {
            int row = m0 + wm * 64 + am * 16 + (lane >> 2);
            #pragma unroll
            for (int bn = 0; bn < 8; bn++) {
                int col = n0 + wn * 64 + bn * 8 + (lane & 3) * 2;
                *(float2*)&C[(size_t)row * ldc + col]       = make_float2(acc[am][bn][0], acc[am][bn][1]);
                *(float2*)&C[(size_t)(row + 8) * ldc + col] = make_float2(acc[am][bn][2], acc[am][bn][3]);
            }
        }
    } else {
        // RoPE (cols < V_OFF) + fp16 hi/lo split -> Oh/Ol
        #pragma unroll
        for (int am = 0; am < 4; am++) {
            int row = m0 + wm * 64 + am * 16 + (lane >> 2);
            #pragma unroll
            for (int bn = 0; bn < 8; bn++) {
                int col = n0 + wn * 64 + bn * 8 + (lane & 3) * 2;
                int i = (col & (HD - 1)) >> 1;
                bool rope = col < V_OFF;
                #pragma unroll
                for (int half = 0; half < 2; half++) {
                    int r = row + half * 8;
                    float v0 = acc[am][bn][2 * half], v1 = acc[am][bn][2 * half + 1];
                    if (rope) {
                        float c = cs[r * 64 + i], si = sn[r * 64 + i];
                        float t0 = v0 * c - v1 * si;
                        float t1 = v0 * si + v1 * c;
                        v0 = t0; v1 = t1;
                    }
                    uint32_t hb, lb;
                    pack_hl_f16(v0, v1, hb, lb);
                    *(uint32_t*)&Oh[(size_t)r * ldc + col] = hb;
                    *(uint32_t*)&Ol[(size_t)r * ldc + col] = lb;
                }
            }
        }
    }
}

// ---------------- tensor-core flash attention (fp16, causal, GQA 4:1) ----------------
// QK^T: (Qh + Ql) * Kh  (2 terms; Kl dropped, never loaded)
// PV:   P * Vh          (1 term;  Vl dropped, never loaded)
// KV stage: Kh 16K + Vh 16K = 32KB, double buffered. Q: Qh+Ql 64KB.
#define ATT_SMEM (128 * 1024)

__global__ __launch_bounds__(256, 1) void attn_mma(
    const __half* __restrict__ qh_g, const __half* __restrict__ ql_g,
    __half* __restrict__ ah_g)
{
    extern __shared__ __align__(1024) char smb[];
    const uint32_t sb = smem_u32(smb);
    const uint32_t sQh = sb, sQl = sb + 32 * 1024;

    const int tid = threadIdx.x, lane = tid & 31, wid = tid >> 5;
    const int qt = (int)gridDim.x - 1 - (int)blockIdx.x;
    const int h = blockIdx.y, kvh = h >> 2;
    const int q0 = qt * 128;
    const int wq = wid * 16;

    #pragma unroll
    for (int i = 0; i < 8; i++) {
        int ch = tid + i * 256;
        int row = ch >> 4, c16 = ch & 15;
        uint32_t so = (uint32_t)(row * 256) + (uint32_t)((c16 ^ (row & 7)) << 4);
        size_t g = (size_t)(q0 + row) * QKV_N + h * HD + c16 * 8;
        cp16(sQh + so, qh_g + g);
        cp16(sQl + so, ql_g + g);
    }
    cp_commit();

    const int ktmax = 2 * qt + 1;
    auto load_kv = [&](int kt) {
        const uint32_t st = sb + 64 * 1024 + (uint32_t)(kt & 1) * 32 * 1024;
        const int k0 = kt * 64;
        #pragma unroll
        for (int i = 0; i < 4; i++) {
            int ch = tid + i * 256;
            int row = ch >> 4, c16 = ch & 15;
            uint32_t so = (uint32_t)(row * 256) + (uint32_t)((c16 ^ (row & 7)) << 4);
            size_t kb = (size_t)(k0 + row) * QKV_N + kvh * HD + c16 * 8;
            cp16(st + so,             qh_g + kb + K_OFF);
            cp16(st + 16 * 1024 + so, qh_g + kb + V_OFF);
        }
        cp_commit();
    };
    load_kv(0);

    float oacc[16][4];
    #pragma unroll
    for (int a = 0; a < 16; a++)
        #pragma unroll
        for (int q = 0; q < 4; q++) oacc[a][q] = 0.f;
    float m0 = -1e30f, m1 = -1e30f, l0 = 0.f, l1 = 0.f;
    const float kscale = 0.08838834764831845f * 1.44269504088896f;

    const int rin = lane & 7, grp = lane >> 3;
    const int arow = wq + rin + (grp & 1) * 8;
    const int r0 = lane >> 2;

    for (int kt = 0; kt <= ktmax; kt++) {
        if (kt < ktmax) { load_kv(kt + 1); cp_wait<1>(); }
        else            { cp_wait<0>(); }
        __syncthreads();

        const bool skip = (kt * 64) > (q0 + wq + 15);
        if (!skip) {
            const uint32_t st = sb + 64 * 1024 + (uint32_t)(kt & 1) * 32 * 1024;

            float sc[8][4];
            #pragma unroll
            for (int a = 0; a < 8; a++)
                #pragma unroll
                for (int q = 0; q < 4; q++) sc[a][q] = 0.f;

            // QK^T: (Qh + Ql) * Kh
            #pragma unroll
            for (int k16 = 0; k16 < 8; k16++) {
                const int c16 = k16 * 2 + (grp >> 1);
                uint32_t aoff = (uint32_t)(arow * 256) + (uint32_t)((c16 ^ (arow & 7)) << 4);
                uint32_t aqh[4], aql[4];
                ldm_x4(aqh, sQh + aoff);
                ldm_x4(aql, sQl + aoff);
                #pragma unroll
                for (int bp = 0; bp < 2; bp++) {
                    uint32_t bh[2][4];
                    #pragma unroll
                    for (int t = 0; t < 2; t++) {
                        int brow = (bp * 2 + t) * 16 + rin + (grp & 1) * 8;
                        uint32_t boff = (uint32_t)(brow * 256) + (uint32_t)((c16 ^ (brow & 7)) << 4);
                        ldm_x4(bh[t], st + boff);
                    }
                    #pragma unroll
                    for (int t = 0; t < 2; t++) {
                        int b = bp * 2 + t;
                        mma_f16(sc[2 * b],     aqh, bh[t][0], bh[t][2]);
                        mma_f16(sc[2 * b + 1], aqh, bh[t][1], bh[t][3]);
                    }
                    #pragma unroll
                    for (int t = 0; t < 2; t++) {
                        int b = bp * 2 + t;
                        mma_f16(sc[2 * b],     aql, bh[t][0], bh[t][2]);
                        mma_f16(sc[2 * b + 1], aql, bh[t][1], bh[t][3]);
                    }
                }
            }

            if (kt * 64 + 63 > q0 + wq) {
                int qr0 = q0 + wq + r0, qr1 = qr0 + 8;
                int cb = kt * 64 + 2 * (lane & 3);
                #pragma unroll
                for (int a = 0; a < 8; a++) {
                    int c0 = cb + a * 8, c1 = c0 + 1;
                    if (c0 > qr0) sc[a][0] = -1e30f;
                    if (c1 > qr0) sc[a][1] = -1e30f;
                    if (c0 > qr1) sc[a][2] = -1e30f;
                    if (c1 > qr1) sc[a][3] = -1e30f;
                }
            }

            float mx0 = -1e30f, mx1 = -1e30f;
            #pragma unroll
            for (int a = 0; a < 8; a++) {
                mx0 = fmaxf(mx0, fmaxf(sc[a][0], sc[a][1]));
                mx1 = fmaxf(mx1, fmaxf(sc[a][2], sc[a][3]));
            }
            mx0 = fmaxf(mx0, __shfl_xor_sync(0xffffffffu, mx0, 1));
            mx0 = fmaxf(mx0, __shfl_xor_sync(0xffffffffu, mx0, 2));
            mx1 = fmaxf(mx1, __shfl_xor_sync(0xffffffffu, mx1, 1));
            mx1 = fmaxf(mx1, __shfl_xor_sync(0xffffffffu, mx1, 2));
            float nm0 = fmaxf(m0, mx0), nm1 = fmaxf(m1, mx1);
            float corr0 = exp2f((m0 - nm0) * kscale);
            float corr1 = exp2f((m1 - nm1) * kscale);
            float s0 = 0.f, s1 = 0.f;
            #pragma unroll
            for (int a = 0; a < 8; a++) {
                sc[a][0] = exp2f((sc[a][0] - nm0) * kscale);
                sc[a][1] = exp2f((sc[a][1] - nm0) * kscale);
                sc[a][2] = exp2f((sc[a][2] - nm1) * kscale);
                sc[a][3] = exp2f((sc[a][3] - nm1) * kscale);
                s0 += sc[a][0] + sc[a][1];
                s1 += sc[a][2] + sc[a][3];
            }
            s0 += __shfl_xor_sync(0xffffffffu, s0, 1);
            s0 += __shfl_xor_sync(0xffffffffu, s0, 2);
            s1 += __shfl_xor_sync(0xffffffffu, s1, 1);
            s1 += __shfl_xor_sync(0xffffffffu, s1, 2);
            l0 = l0 * corr0 + s0;
            l1 = l1 * corr1 + s1;
            m0 = nm0; m1 = nm1;
            #pragma unroll
            for (int a = 0; a < 16; a++) {
                oacc[a][0] *= corr0; oacc[a][1] *= corr0;
                oacc[a][2] *= corr1; oacc[a][3] *= corr1;
            }

            // PV: P * Vh (1 term)
            #pragma unroll
            for (int t = 0; t < 4; t++) {
                uint32_t ph[4];
                ph[0] = pack_f16(sc[2 * t][0],     sc[2 * t][1]);
                ph[1] = pack_f16(sc[2 * t][2],     sc[2 * t][3]);
                ph[2] = pack_f16(sc[2 * t + 1][0], sc[2 * t + 1][1]);
                ph[3] = pack_f16(sc[2 * t + 1][2], sc[2 * t + 1][3]);
                #pragma unroll
                for (int dp = 0; dp < 4; dp++) {
                    uint32_t vh[2][4];
                    #pragma unroll
                    for (int u = 0; u < 2; u++) {
                        int d = dp * 2 + u;
                        int vrow = t * 16 + (grp & 1) * 8 + rin;
                        int c16 = d * 2 + (grp >> 1);
                        uint32_t voff = (uint32_t)(vrow * 256) + (uint32_t)((c16 ^ (vrow & 7)) << 4);
                        ldm_x4t(vh[u], st + 16 * 1024 + voff);
                    }
                    #pragma unroll
                    for (int u = 0; u < 2; u++) {
                        int d = dp * 2 + u;
                        mma_f16(oacc[2 * d],     ph, vh[u][0], vh[u][1]);
                        mma_f16(oacc[2 * d + 1], ph, vh[u][2], vh[u][3]);
                    }
                }
            }
        }
        __syncthreads();
    }

    float inv0 = 1.f / l0, inv1 = 1.f / l1;
    int gr0 = q0 + wq + r0, gr1 = gr0 + 8;
    #pragma unroll
    for (int a = 0; a < 16; a++) {
        int d0 = a * 8 + 2 * (lane & 3);
        *(uint32_t*)&ah_g[(size_t)gr0 * DIM + h * HD + d0] =
            pack_f16(oacc[a][0] * inv0, oacc[a][1] * inv0);
        *(uint32_t*)&ah_g[(size_t)gr1 * DIM + h * HD + d0] =
            pack_f16(oacc[a][2] * inv1, oacc[a][3] * inv1);
    }
}

// ---------------- launch ----------------
extern "C" void kernel_launch(void* const* d_in, const int* in_sizes, int n_in,
                              void* d_out, int out_size)
{
    const float* x  = (const float*)d_in[0];
    const float* fc = (const float*)d_in[1];
    const float* fs = (const float*)d_in[2];
    const float* wq = (const float*)d_in[5];
    const float* wk = (const float*)d_in[6];
    const float* wv = (const float*)d_in[7];
    const float* wo = (const float*)d_in[8];
    float* out = (float*)d_out;

    __half *qh, *ql, *xh, *wh, *oh, *ah;
    cudaGetSymbolAddress((void**)&qh, g_qh);  cudaGetSymbolAddress((void**)&ql, g_ql);
    cudaGetSymbolAddress((void**)&xh, g_xh);
    cudaGetSymbolAddress((void**)&wh, g_wh);  cudaGetSymbolAddress((void**)&oh, g_oh);
    cudaGetSymbolAddress((void**)&ah, g_ah);

    cudaFuncSetAttribute(gemm_f16, cudaFuncAttributeMaxDynamicSharedMemorySize, GEMM_SMEM);
    cudaFuncSetAttribute(attn_mma, cudaFuncAttributeMaxDynamicSharedMemorySize, ATT_SMEM);

    dim3 blk(256);
    int n4x = S * DIM / 4;
    split_f16h<<<(n4x + 255) / 256, blk>>>(x, xh, n4x);
    int n4w = 2 * NQ4 + 2 * NK4;
    split_weights<<<(n4w + 255) / 256, blk>>>(wq, wk, wv, wo, wh, oh);

    // QKV projection (fp16 1-term) with fused RoPE + fp16 hi/lo split epilogue
    gemm_f16<<<dim3(S / 128, QKV_N / 256), blk, GEMM_SMEM>>>(
        xh, nullptr, wh, nullptr, DIM, QKV_N, 1, 1, fc, fs, qh, ql);

    // tensor-core attention (fp16, QK 2-term / PV 1-term) -> fp16 hi output
    attn_mma<<<dim3(S / 128, NH), blk, ATT_SMEM>>>(qh, ql, ah);

    // output projection (fp16 1-term) -> fp32 out
    gemm_f16<<<dim3(S / 128, DIM / 256), blk, GEMM_SMEM>>>(
        ah, nullptr, oh, out, DIM, DIM, 0, 1, nullptr, nullptr, nullptr, nullptr);
}

// round 12
// speedup vs baseline: 2.3818x; 1.1826x over previous
#include <cuda_runtime.h>
#include <cuda_bf16.h>
#include <cuda_fp16.h>
#include <cstdint>

// ---------------- problem constants ----------------
#define S       2048
#define DIM     4096
#define NH      32
#define HD      128
#define QKV_N   6144
#define K_OFF   4096
#define V_OFF   5120

// ---------------- scratch (device globals) ----------------
__device__ __half g_qh[S * QKV_N], g_ql[S * QKV_N];   // rope'd qkv, fp16 hi/lo
__device__ __half g_xh[S * DIM];                      // x fp16 hi
__device__ __half g_wh[QKV_N * DIM];                  // packed wq|wk|wv fp16 hi
__device__ __half g_oh[DIM * DIM];                    // wo fp16 hi
__device__ __half g_ah[S * DIM];                      // attention out fp16 hi

// ---------------- helpers ----------------
__device__ __forceinline__ uint32_t smem_u32(const void* p) {
    uint32_t a;
    asm("{ .reg .u64 t; cvta.to.shared.u64 t, %1; cvt.u32.u64 %0, t; }" : "=r"(a) : "l"(p));
    return a;
}
__device__ __forceinline__ void cp16(uint32_t dst, const void* src) {
    asm volatile("cp.async.cg.shared.global [%0], [%1], 16;" :: "r"(dst), "l"(src));
}
__device__ __forceinline__ void cp_commit() {
    asm volatile("cp.async.commit_group;");
}
template <int N>
__device__ __forceinline__ void cp_wait() {
    asm volatile("cp.async.wait_group %0;" :: "n"(N));
}
__device__ __forceinline__ void ldm_x4(uint32_t* r, uint32_t addr) {
    asm volatile("ldmatrix.sync.aligned.m8n8.x4.shared.b16 {%0,%1,%2,%3}, [%4];"
                 : "=r"(r[0]), "=r"(r[1]), "=r"(r[2]), "=r"(r[3]) : "r"(addr));
}
__device__ __forceinline__ void ldm_x4t(uint32_t* r, uint32_t addr) {
    asm volatile("ldmatrix.sync.aligned.m8n8.x4.trans.shared.b16 {%0,%1,%2,%3}, [%4];"
                 : "=r"(r[0]), "=r"(r[1]), "=r"(r[2]), "=r"(r[3]) : "r"(addr));
}
__device__ __forceinline__ void mma_f16(float* c, const uint32_t* a, uint32_t b0, uint32_t b1) {
    asm volatile(
        "mma.sync.aligned.m16n8k16.row.col.f32.f16.f16.f32 "
        "{%0,%1,%2,%3}, {%4,%5,%6,%7}, {%8,%9}, {%0,%1,%2,%3};"
        : "+f"(c[0]), "+f"(c[1]), "+f"(c[2]), "+f"(c[3])
        : "r"(a[0]), "r"(a[1]), "r"(a[2]), "r"(a[3]), "r"(b0), "r"(b1));
}
__device__ __forceinline__ void pack_hl_f16(float x, float y, uint32_t& h, uint32_t& l) {
    __half2 hb = __floats2half2_rn(x, y);
    float hx = __low2float(hb), hy = __high2float(hb);
    __half2 lb = __floats2half2_rn(x - hx, y - hy);
    h = *reinterpret_cast<uint32_t*>(&hb);
    l = *reinterpret_cast<uint32_t*>(&lb);
}
__device__ __forceinline__ uint32_t pack_f16(float x, float y) {
    __half2 hb = __floats2half2_rn(x, y);
    return *reinterpret_cast<uint32_t*>(&hb);
}

// ---------------- splits ----------------
__global__ void split_f16h(const float* __restrict__ src, __half* __restrict__ hi, int n4)
{
    int i = blockIdx.x * blockDim.x + threadIdx.x;
    if (i >= n4) return;
    float4 v = ((const float4*)src)[i];
    ((__half2*)hi)[2 * i]     = __floats2half2_rn(v.x, v.y);
    ((__half2*)hi)[2 * i + 1] = __floats2half2_rn(v.z, v.w);
}

#define NQ4 (DIM * DIM / 4)
#define NK4 (1024 * DIM / 4)
__global__ void split_weights(const float* __restrict__ wq, const float* __restrict__ wk,
                              const float* __restrict__ wv, const float* __restrict__ wo,
                              __half* __restrict__ wh, __half* __restrict__ oh)
{
    int i = blockIdx.x * blockDim.x + threadIdx.x;
    if (i >= 2 * NQ4 + 2 * NK4) return;
    const float* src;
    __half* dst;
    int j;
    if (i < NQ4)                 { j = i;                src = wq; dst = wh; }
    else if (i < NQ4 + NK4)      { j = i - NQ4;          src = wk; dst = wh + (size_t)4096 * DIM; }
    else if (i < NQ4 + 2 * NK4)  { j = i - NQ4 - NK4;    src = wv; dst = wh + (size_t)5120 * DIM; }
    else                         { j = i - NQ4 - 2*NK4;  src = wo; dst = oh; }
    float4 v = ((const float4*)src)[j];
    ((__half2*)dst)[2 * j]     = __floats2half2_rn(v.x, v.y);
    ((__half2*)dst)[2 * j + 1] = __floats2half2_rn(v.z, v.w);
}

// ---------------- fp16 1-term GEMM, CTA 128x128, warp 32x64, 3-stage, 2 CTAs/SM ----
// C = Ah*Bh. mode 0: fp32 C; mode 1: RoPE (cols < V_OFF) + fp16 hi/lo split -> Oh/Ol
#define GA_HI 0
#define GB_HI (16 * 1024)
#define GSTG  (32 * 1024)
#define GEMM_SMEM (3 * GSTG)          // 96 KB -> 2 CTAs/SM

__global__ __launch_bounds__(256, 2) void gemm_f16(
    const __half* __restrict__ Ah, const __half* __restrict__ Bh,
    float* __restrict__ C, int K, int ldc, int mode,
    const float* __restrict__ cs, const float* __restrict__ sn,
    __half* __restrict__ Oh, __half* __restrict__ Ol)
{
    extern __shared__ __align__(1024) char smc[];
    const uint32_t sbase = smem_u32(smc);

    const int tid  = threadIdx.x;
    const int lane = tid & 31;
    const int wid  = tid >> 5;
    const int wm   = wid & 3;           // 4 m-quarters of 32
    const int wn   = wid >> 2;          // 2 n-halves of 64
    const int m0 = blockIdx.x * 128;
    const int n0 = blockIdx.y * 128;

    const int grp = lane >> 3;
    const int rin = lane & 7;

    float acc[2][8][4];
    #pragma unroll
    for (int i = 0; i < 2; i++)
        #pragma unroll
        for (int j = 0; j < 8; j++)
            #pragma unroll
            for (int q = 0; q < 4; q++) acc[i][j][q] = 0.f;

    const int nk = K >> 6;

    auto load_chunk = [&](int it) {
        const int k0 = it << 6;
        const uint32_t sb = sbase + (uint32_t)(it % 3) * GSTG;
        #pragma unroll
        for (int i = 0; i < 4; i++) {                   // A: 1024 16B-lines
            int id = tid + i * 256;
            int row = id >> 3, c16 = id & 7;
            uint32_t so = (uint32_t)(row * 128) + ((uint32_t)(c16 ^ (row & 7)) << 4);
            size_t g = (size_t)(m0 + row) * K + k0 + c16 * 8;
            cp16(sb + GA_HI + so, Ah + g);
        }
        #pragma unroll
        for (int i = 0; i < 4; i++) {                   // B: 1024 16B-lines
            int id = tid + i * 256;
            int row = id >> 3, c16 = id & 7;
            uint32_t so = (uint32_t)(row * 128) + ((uint32_t)(c16 ^ (row & 7)) << 4);
            size_t g = (size_t)(n0 + row) * K + k0 + c16 * 8;
            cp16(sb + GB_HI + so, Bh + g);
        }
        cp_commit();
    };

    load_chunk(0);
    if (nk > 1) load_chunk(1); else cp_commit();

    for (int it = 0; it < nk; it++) {
        if (it + 2 < nk) load_chunk(it + 2); else cp_commit();
        cp_wait<2>();
        __syncthreads();

        const uint32_t sA = sbase + (uint32_t)(it % 3) * GSTG;
        const uint32_t sB = sA + GB_HI;
        #pragma unroll
        for (int kc = 0; kc < 4; kc++) {
            const int c16 = kc * 2 + (grp >> 1);

            uint32_t ah[2][4];
            #pragma unroll
            for (int am = 0; am < 2; am++) {
                int row = wm * 32 + am * 16 + rin + (grp & 1) * 8;
                uint32_t so = (uint32_t)(row * 128) + ((uint32_t)(c16 ^ (row & 7)) << 4);
                ldm_x4(ah[am], sA + so);
            }
            #pragma unroll
            for (int bt = 0; bt < 4; bt++) {
                int row = wn * 64 + bt * 16 + rin + (grp & 1) * 8;
                uint32_t so = (uint32_t)(row * 128) + ((uint32_t)(c16 ^ (row & 7)) << 4);
                uint32_t bh[4];
                ldm_x4(bh, sB + so);
                #pragma unroll
                for (int am = 0; am < 2; am++) {
                    mma_f16(acc[am][2 * bt],     ah[am], bh[0], bh[2]);
                    mma_f16(acc[am][2 * bt + 1], ah[am], bh[1], bh[3]);
                }
            }
        }
        __syncthreads();
    }

    if (mode == 0) {
        #pragma unroll
        for (int am = 0; am < 2; am++) {
            int row = m0 + wm * 32 + am * 16 + (lane >> 2);
            #pragma unroll
            for (int bn = 0; bn < 8; bn++) {
                int col = n0 + wn * 64 + bn * 8 + (lane & 3) * 2;
                *(float2*)&C[(size_t)row * ldc + col]       = make_float2(acc[am][bn][0], acc[am][bn][1]);
                *(float2*)&C[(size_t)(row + 8) * ldc + col] = make_float2(acc[am][bn][2], acc[am][bn][3]);
            }
        }
    } else {
        #pragma unroll
        for (int am = 0; am < 2; am++) {
            int row = m0 + wm * 32 + am * 16 + (lane >> 2);
            #pragma unroll
            for (int bn = 0; bn < 8; bn++) {
                int col = n0 + wn * 64 + bn * 8 + (lane & 3) * 2;
                int i = (col & (HD - 1)) >> 1;
                bool rope = col < V_OFF;
                #pragma unroll
                for (int half = 0; half < 2; half++) {
                    int r = row + half * 8;
                    float v0 = acc[am][bn][2 * half], v1 = acc[am][bn][2 * half + 1];
                    if (rope) {
                        float c = cs[r * 64 + i], si = sn[r * 64 + i];
                        float t0 = v0 * c - v1 * si;
                        float t1 = v0 * si + v1 * c;
                        v0 = t0; v1 = t1;
                    }
                    uint32_t hb, lb;
                    pack_hl_f16(v0, v1, hb, lb);
                    *(uint32_t*)&Oh[(size_t)r * ldc + col] = hb;
                    *(uint32_t*)&Ol[(size_t)r * ldc + col] = lb;
                }
            }
        }
    }
}

// ---------------- tensor-core flash attention (fp16, causal, GQA 4:1) ----------------
// QK^T: (Qh + Ql) * Kh ; PV: P * Vh
#define ATT_SMEM (128 * 1024)

__global__ __launch_bounds__(256, 1) void attn_mma(
    const __half* __restrict__ qh_g, const __half* __restrict__ ql_g,
    __half* __restrict__ ah_g)
{
    extern __shared__ __align__(1024) char smb[];
    const uint32_t sb = smem_u32(smb);
    const uint32_t sQh = sb, sQl = sb + 32 * 1024;

    const int tid = threadIdx.x, lane = tid & 31, wid = tid >> 5;
    const int qt = (int)gridDim.x - 1 - (int)blockIdx.x;
    const int h = blockIdx.y, kvh = h >> 2;
    const int q0 = qt * 128;
    const int wq = wid * 16;

    #pragma unroll
    for (int i = 0; i < 8; i++) {
        int ch = tid + i * 256;
        int row = ch >> 4, c16 = ch & 15;
        uint32_t so = (uint32_t)(row * 256) + (uint32_t)((c16 ^ (row & 7)) << 4);
        size_t g = (size_t)(q0 + row) * QKV_N + h * HD + c16 * 8;
        cp16(sQh + so, qh_g + g);
        cp16(sQl + so, ql_g + g);
    }
    cp_commit();

    const int ktmax = 2 * qt + 1;
    auto load_kv = [&](int kt) {
        const uint32_t st = sb + 64 * 1024 + (uint32_t)(kt & 1) * 32 * 1024;
        const int k0 = kt * 64;
        #pragma unroll
        for (int i = 0; i < 4; i++) {
            int ch = tid + i * 256;
            int row = ch >> 4, c16 = ch & 15;
            uint32_t so = (uint32_t)(row * 256) + (uint32_t)((c16 ^ (row & 7)) << 4);
            size_t kb = (size_t)(k0 + row) * QKV_N + kvh * HD + c16 * 8;
            cp16(st + so,             qh_g + kb + K_OFF);
            cp16(st + 16 * 1024 + so, qh_g + kb + V_OFF);
        }
        cp_commit();
    };
    load_kv(0);

    float oacc[16][4];
    #pragma unroll
    for (int a = 0; a < 16; a++)
        #pragma unroll
        for (int q = 0; q < 4; q++) oacc[a][q] = 0.f;
    float m0 = -1e30f, m1 = -1e30f, l0 = 0.f, l1 = 0.f;
    const float kscale = 0.08838834764831845f * 1.44269504088896f;

    const int rin = lane & 7, grp = lane >> 3;
    const int arow = wq + rin + (grp & 1) * 8;
    const int r0 = lane >> 2;

    for (int kt = 0; kt <= ktmax; kt++) {
        if (kt < ktmax) { load_kv(kt + 1); cp_wait<1>(); }
        else            { cp_wait<0>(); }
        __syncthreads();

        const bool skip = (kt * 64) > (q0 + wq + 15);
        if (!skip) {
            const uint32_t st = sb + 64 * 1024 + (uint32_t)(kt & 1) * 32 * 1024;

            float sc[8][4];
            #pragma unroll
            for (int a = 0; a < 8; a++)
                #pragma unroll
                for (int q = 0; q < 4; q++) sc[a][q] = 0.f;

            #pragma unroll
            for (int k16 = 0; k16 < 8; k16++) {
                const int c16 = k16 * 2 + (grp >> 1);
                uint32_t aoff = (uint32_t)(arow * 256) + (uint32_t)((c16 ^ (arow & 7)) << 4);
                uint32_t aqh[4], aql[4];
                ldm_x4(aqh, sQh + aoff);
                ldm_x4(aql, sQl + aoff);
                #pragma unroll
                for (int bp = 0; bp < 2; bp++) {
                    uint32_t bh[2][4];
                    #pragma unroll
                    for (int t = 0; t < 2; t++) {
                        int brow = (bp * 2 + t) * 16 + rin + (grp & 1) * 8;
                        uint32_t boff = (uint32_t)(brow * 256) + (uint32_t)((c16 ^ (brow & 7)) << 4);
                        ldm_x4(bh[t], st + boff);
                    }
                    #pragma unroll
                    for (int t = 0; t < 2; t++) {
                        int b = bp * 2 + t;
                        mma_f16(sc[2 * b],     aqh, bh[t][0], bh[t][2]);
                        mma_f16(sc[2 * b + 1], aqh, bh[t][1], bh[t][3]);
                    }
                    #pragma unroll
                    for (int t = 0; t < 2; t++) {
                        int b = bp * 2 + t;
                        mma_f16(sc[2 * b],     aql, bh[t][0], bh[t][2]);
                        mma_f16(sc[2 * b + 1], aql, bh[t][1], bh[t][3]);
                    }
                }
            }

            if (kt * 64 + 63 > q0 + wq) {
                int qr0 = q0 + wq + r0, qr1 = qr0 + 8;
                int cb = kt * 64 + 2 * (lane & 3);
                #pragma unroll
                for (int a = 0; a < 8; a++) {
                    int c0 = cb + a * 8, c1 = c0 + 1;
                    if (c0 > qr0) sc[a][0] = -1e30f;
                    if (c1 > qr0) sc[a][1] = -1e30f;
                    if (c0 > qr1) sc[a][2] = -1e30f;
                    if (c1 > qr1) sc[a][3] = -1e30f;
                }
            }

            float mx0 = -1e30f, mx1 = -1e30f;
            #pragma unroll
            for (int a = 0; a < 8; a++) {
                mx0 = fmaxf(mx0, fmaxf(sc[a][0], sc[a][1]));
                mx1 = fmaxf(mx1, fmaxf(sc[a][2], sc[a][3]));
            }
            mx0 = fmaxf(mx0, __shfl_xor_sync(0xffffffffu, mx0, 1));
            mx0 = fmaxf(mx0, __shfl_xor_sync(0xffffffffu, mx0, 2));
            mx1 = fmaxf(mx1, __shfl_xor_sync(0xffffffffu, mx1, 1));
            mx1 = fmaxf(mx1, __shfl_xor_sync(0xffffffffu, mx1, 2));
            float nm0 = fmaxf(m0, mx0), nm1 = fmaxf(m1, mx1);
            float corr0 = exp2f((m0 - nm0) * kscale);
            float corr1 = exp2f((m1 - nm1) * kscale);
            float s0 = 0.f, s1 = 0.f;
            #pragma unroll
            for (int a = 0; a < 8; a++) {
                sc[a][0] = exp2f((sc[a][0] - nm0) * kscale);
                sc[a][1] = exp2f((sc[a][1] - nm0) * kscale);
                sc[a][2] = exp2f((sc[a][2] - nm1) * kscale);
                sc[a][3] = exp2f((sc[a][3] - nm1) * kscale);
                s0 += sc[a][0] + sc[a][1];
                s1 += sc[a][2] + sc[a][3];
            }
            s0 += __shfl_xor_sync(0xffffffffu, s0, 1);
            s0 += __shfl_xor_sync(0xffffffffu, s0, 2);
            s1 += __shfl_xor_sync(0xffffffffu, s1, 1);
            s1 += __shfl_xor_sync(0xffffffffu, s1, 2);
            l0 = l0 * corr0 + s0;
            l1 = l1 * corr1 + s1;
            m0 = nm0; m1 = nm1;
            #pragma unroll
            for (int a = 0; a < 16; a++) {
                oacc[a][0] *= corr0; oacc[a][1] *= corr0;
                oacc[a][2] *= corr1; oacc[a][3] *= corr1;
            }

            #pragma unroll
            for (int t = 0; t < 4; t++) {
                uint32_t ph[4];
                ph[0] = pack_f16(sc[2 * t][0],     sc[2 * t][1]);
                ph[1] = pack_f16(sc[2 * t][2],     sc[2 * t][3]);
                ph[2] = pack_f16(sc[2 * t + 1][0], sc[2 * t + 1][1]);
                ph[3] = pack_f16(sc[2 * t + 1][2], sc[2 * t + 1][3]);
                #pragma unroll
                for (int dp = 0; dp < 4; dp++) {
                    uint32_t vh[2][4];
                    #pragma unroll
                    for (int u = 0; u < 2; u++) {
                        int d = dp * 2 + u;
                        int vrow = t * 16 + (grp & 1) * 8 + rin;
                        int c16 = d * 2 + (grp >> 1);
                        uint32_t voff = (uint32_t)(vrow * 256) + (uint32_t)((c16 ^ (vrow & 7)) << 4);
                        ldm_x4t(vh[u], st + 16 * 1024 + voff);
                    }
                    #pragma unroll
                    for (int u = 0; u < 2; u++) {
                        int d = dp * 2 + u;
                        mma_f16(oacc[2 * d],     ph, vh[u][0], vh[u][1]);
                        mma_f16(oacc[2 * d + 1], ph, vh[u][2], vh[u][3]);
                    }
                }
            }
        }
        __syncthreads();
    }

    float inv0 = 1.f / l0, inv1 = 1.f / l1;
    int gr0 = q0 + wq + r0, gr1 = gr0 + 8;
    #pragma unroll
    for (int a = 0; a < 16; a++) {
        int d0 = a * 8 + 2 * (lane & 3);
        *(uint32_t*)&ah_g[(size_t)gr0 * DIM + h * HD + d0] =
            pack_f16(oacc[a][0] * inv0, oacc[a][1] * inv0);
        *(uint32_t*)&ah_g[(size_t)gr1 * DIM + h * HD + d0] =
            pack_f16(oacc[a][2] * inv1, oacc[a][3] * inv1);
    }
}

// ---------------- launch ----------------
extern "C" void kernel_launch(void* const* d_in, const int* in_sizes, int n_in,
                              void* d_out, int out_size)
{
    const float* x  = (const float*)d_in[0];
    const float* fc = (const float*)d_in[1];
    const float* fs = (const float*)d_in[2];
    const float* wq = (const float*)d_in[5];
    const float* wk = (const float*)d_in[6];
    const float* wv = (const float*)d_in[7];
    const float* wo = (const float*)d_in[8];
    float* out = (float*)d_out;

    __half *qh, *ql, *xh, *wh, *oh, *ah;
    cudaGetSymbolAddress((void**)&qh, g_qh);  cudaGetSymbolAddress((void**)&ql, g_ql);
    cudaGetSymbolAddress((void**)&xh, g_xh);
    cudaGetSymbolAddress((void**)&wh, g_wh);  cudaGetSymbolAddress((void**)&oh, g_oh);
    cudaGetSymbolAddress((void**)&ah, g_ah);

    cudaFuncSetAttribute(gemm_f16, cudaFuncAttributeMaxDynamicSharedMemorySize, GEMM_SMEM);
    cudaFuncSetAttribute(attn_mma, cudaFuncAttributeMaxDynamicSharedMemorySize, ATT_SMEM);

    dim3 blk(256);
    int n4x = S * DIM / 4;
    split_f16h<<<(n4x + 255) / 256, blk>>>(x, xh, n4x);
    int n4w = 2 * NQ4 + 2 * NK4;
    split_weights<<<(n4w + 255) / 256, blk>>>(wq, wk, wv, wo, wh, oh);

    // QKV projection (fp16 1-term) with fused RoPE + fp16 hi/lo split epilogue
    gemm_f16<<<dim3(S / 128, QKV_N / 128), blk, GEMM_SMEM>>>(
        xh, wh, nullptr, DIM, QKV_N, 1, fc, fs, qh, ql);

    // tensor-core attention (fp16, QK 2-term / PV 1-term) -> fp16 hi output
    attn_mma<<<dim3(S / 128, NH), blk, ATT_SMEM>>>(qh, ql, ah);

    // output projection (fp16 1-term) -> fp32 out
    gemm_f16<<<dim3(S / 128, DIM / 128), blk, GEMM_SMEM>>>(
        ah, oh, out, DIM, DIM, 0, nullptr, nullptr, nullptr, nullptr);
}